// round 1
// baseline (speedup 1.0000x reference)
#include <cuda_runtime.h>
#include <math.h>

// Problem sizes (fixed)
#define NR   65536
#define DIN  512
#define HD   128
#define DD   32
#define KC   1024
#define EPSBN 1e-5f

// ---------------- scratch (device globals; no allocations) ----------------
__device__ float g_h1[NR * HD];        // encoder hidden pre-BN   (33.5 MB)
__device__ float g_z[NR * DD];         // encoder output          (8 MB)
__device__ int   g_topic[NR];
__device__ float g_colsum[HD];
__device__ float g_colsumsq[HD];
__device__ float g_escale[HD];         // gamma * rstd
__device__ float g_eshift[HD];         // beta - mean*scale
__device__ float g_cbnorm[KC];
__device__ float g_cbproj[KC * HD];    // codebook @ dec_w1 + dec_b1
__device__ int   g_count[KC];
__device__ float g_dscale[HD];
__device__ float g_dshift[HD];
__device__ float g_decoded[KC * DIN];  // decoded codewords (2 MB)
__device__ float g_zloss;
__device__ float g_recon;

// ---------------- init: zero accumulators every call ----------------
__global__ void k_init() {
    int t = blockIdx.x * blockDim.x + threadIdx.x;
    if (t < HD) { g_colsum[t] = 0.f; g_colsumsq[t] = 0.f; }
    if (t < KC) g_count[t] = 0;
    if (t == 0) { g_zloss = 0.f; g_recon = 0.f; }
}

// ---------------- GEMM1: h1 = X[65536,512] @ W[512,128] + b ----------------
// classic 128x128x8 fp32 tiling, 256 threads, 8x8 per thread
__global__ __launch_bounds__(256, 2) void k_gemm1(const float* __restrict__ X,
                                                  const float* __restrict__ W,
                                                  const float* __restrict__ B) {
    __shared__ float As[8][128];   // [k][m]
    __shared__ float Bs[8][128];   // [k][n]
    int tid = threadIdx.x;
    int row0 = blockIdx.x * 128;
    int tr = (tid >> 4) << 3;      // 0..120
    int tc = (tid & 15) << 3;      // 0..120
    float acc[8][8] = {};

    int ar = tid >> 1;             // 0..127
    int ac = (tid & 1) << 2;       // 0 or 4
    int br = tid >> 5;             // 0..7
    int bc = (tid & 31) << 2;      // 0..124
    const float* Xbase = X + (row0 + ar) * DIN + ac;

    for (int kk = 0; kk < DIN; kk += 8) {
        float4 av = *(const float4*)(Xbase + kk);
        float4 bv = *(const float4*)(W + (kk + br) * HD + bc);
        __syncthreads();
        As[ac + 0][ar] = av.x;
        As[ac + 1][ar] = av.y;
        As[ac + 2][ar] = av.z;
        As[ac + 3][ar] = av.w;
        *(float4*)&Bs[br][bc] = bv;
        __syncthreads();
#pragma unroll
        for (int k = 0; k < 8; k++) {
            float a[8], b[8];
            *(float4*)(a)     = *(const float4*)&As[k][tr];
            *(float4*)(a + 4) = *(const float4*)&As[k][tr + 4];
            *(float4*)(b)     = *(const float4*)&Bs[k][tc];
            *(float4*)(b + 4) = *(const float4*)&Bs[k][tc + 4];
#pragma unroll
            for (int i = 0; i < 8; i++)
#pragma unroll
                for (int j = 0; j < 8; j++) acc[i][j] = fmaf(a[i], b[j], acc[i][j]);
        }
    }
#pragma unroll
    for (int i = 0; i < 8; i++) {
        int r = row0 + tr + i;
#pragma unroll
        for (int j = 0; j < 8; j += 4) {
            float4 v;
            v.x = acc[i][j + 0] + B[tc + j + 0];
            v.y = acc[i][j + 1] + B[tc + j + 1];
            v.z = acc[i][j + 2] + B[tc + j + 2];
            v.w = acc[i][j + 3] + B[tc + j + 3];
            *(float4*)&g_h1[r * HD + tc + j] = v;
        }
    }
}

// ---------------- per-column sum / sumsq over h1 ----------------
__global__ __launch_bounds__(128) void k_colstats() {
    int j = threadIdx.x;           // column
    int base = blockIdx.x * 256 * HD;
    float s = 0.f, sq = 0.f;
#pragma unroll 4
    for (int r = 0; r < 256; r++) {
        float v = g_h1[base + r * HD + j];
        s += v;
        sq += v * v;
    }
    atomicAdd(&g_colsum[j], s);
    atomicAdd(&g_colsumsq[j], sq);
}

__global__ void k_bnfin(const float* __restrict__ G, const float* __restrict__ BE) {
    int j = threadIdx.x;  // 128
    float mean = g_colsum[j] * (1.f / (float)NR);
    float var  = g_colsumsq[j] * (1.f / (float)NR) - mean * mean;
    float sc = G[j] * rsqrtf(var + EPSBN);
    g_escale[j] = sc;
    g_eshift[j] = BE[j] - mean * sc;
}

// ---------------- GEMM2: z = relu(bn(h1)) @ W2[128,32] + b2 ----------------
// warp-per-row: lane = output column, h1 row held in float4 regs, shfl broadcast
__global__ __launch_bounds__(256) void k_gemm2(const float* __restrict__ W2,
                                               const float* __restrict__ B2) {
    __shared__ float ws[HD * DD];
    int tid = threadIdx.x;
#pragma unroll
    for (int i = 0; i < 4; i++)
        ((float4*)ws)[tid + i * 256] = ((const float4*)W2)[tid + i * 256];
    __syncthreads();

    int warp = tid >> 5, lane = tid & 31;
    float bias = B2[lane];
    float4 msc = ((const float4*)g_escale)[lane];  // cols 4*lane..4*lane+3
    float4 msh = ((const float4*)g_eshift)[lane];
    int row0 = blockIdx.x * 256 + warp * 32;

    for (int rr = 0; rr < 32; rr++) {
        int row = row0 + rr;
        float4 h = ((const float4*)g_h1)[row * 32 + lane];
        h.x = fmaxf(fmaf(h.x, msc.x, msh.x), 0.f);
        h.y = fmaxf(fmaf(h.y, msc.y, msh.y), 0.f);
        h.z = fmaxf(fmaf(h.z, msc.z, msh.z), 0.f);
        h.w = fmaxf(fmaf(h.w, msc.w, msh.w), 0.f);
        float acc = bias;
#pragma unroll 16
        for (int j = 0; j < HD; j++) {
            float hv = ((j & 3) == 0) ? h.x : ((j & 3) == 1) ? h.y : ((j & 3) == 2) ? h.z : h.w;
            float a = __shfl_sync(0xffffffffu, hv, j >> 2);
            acc = fmaf(a, ws[j * DD + lane], acc);
        }
        g_z[row * DD + lane] = acc;
    }
}

// ---------------- codebook squared norms ----------------
__global__ void k_cbnorm(const float* __restrict__ cb) {
    int k = blockIdx.x * 256 + threadIdx.x;
    const float4* c = (const float4*)(cb + k * DD);
    float s = 0.f;
#pragma unroll
    for (int i = 0; i < 8; i++) {
        float4 v = c[i];
        s += v.x * v.x + v.y * v.y + v.z * v.z + v.w * v.w;
    }
    g_cbnorm[k] = s;
}

// ---------------- distance + argmin + z_loss + histogram ----------------
// codebook (128KB) + norms in dynamic smem, one row per thread
__global__ __launch_bounds__(512) void k_dist(const float* __restrict__ cb) {
    extern __shared__ float sm[];
    float* cs = sm;               // 1024*32
    float* cn = sm + KC * DD;     // 1024
    int tid = threadIdx.x;
#pragma unroll
    for (int i = 0; i < 16; i++)
        ((float4*)cs)[tid + i * 512] = ((const float4*)cb)[tid + i * 512];
    cn[tid]       = g_cbnorm[tid];
    cn[tid + 512] = g_cbnorm[tid + 512];
    __syncthreads();

    int n = blockIdx.x * 512 + tid;
    float4 z[8];
#pragma unroll
    for (int i = 0; i < 8; i++) z[i] = ((const float4*)g_z)[n * 8 + i];
    float zn = 0.f;
#pragma unroll
    for (int i = 0; i < 8; i++)
        zn += z[i].x * z[i].x + z[i].y * z[i].y + z[i].z * z[i].z + z[i].w * z[i].w;

    float best = 3.4e38f;
    int bi = 0;
#pragma unroll 2
    for (int k = 0; k < KC; k++) {
        const float4* c = (const float4*)(cs + (k << 5));
        float d0 = 0.f, d1 = 0.f, d2 = 0.f, d3 = 0.f;
#pragma unroll
        for (int i = 0; i < 8; i += 4) {
            float4 c0 = c[i], c1 = c[i + 1], c2 = c[i + 2], c3 = c[i + 3];
            d0 += z[i].x * c0.x + z[i].y * c0.y + z[i].z * c0.z + z[i].w * c0.w;
            d1 += z[i+1].x * c1.x + z[i+1].y * c1.y + z[i+1].z * c1.z + z[i+1].w * c1.w;
            d2 += z[i+2].x * c2.x + z[i+2].y * c2.y + z[i+2].z * c2.z + z[i+2].w * c2.w;
            d3 += z[i+3].x * c3.x + z[i+3].y * c3.y + z[i+3].z * c3.z + z[i+3].w * c3.w;
        }
        float dot = (d0 + d1) + (d2 + d3);
        float d = (zn + cn[k]) - 2.f * dot;
        if (d < best) { best = d; bi = k; }   // strict < keeps first index (argmin semantics)
    }
    g_topic[n] = bi;
    atomicAdd(&g_count[bi], 1);

    float s = best;
#pragma unroll
    for (int off = 16; off; off >>= 1) s += __shfl_xor_sync(0xffffffffu, s, off);
    if ((tid & 31) == 0) atomicAdd(&g_zloss, s);
}

// ---------------- cbproj = codebook @ dec_w1 + dec_b1  [1024,128] ----------
__global__ __launch_bounds__(128) void k_cbproj(const float* __restrict__ cb,
                                                const float* __restrict__ W1,
                                                const float* __restrict__ B1) {
    __shared__ float row[DD];
    int tid = threadIdx.x;
    if (tid < 8) ((float4*)row)[tid] = ((const float4*)cb)[blockIdx.x * 8 + tid];
    __syncthreads();
    float acc = B1[tid];
#pragma unroll
    for (int d = 0; d < DD; d++) acc = fmaf(row[d], W1[d * HD + tid], acc);
    g_cbproj[blockIdx.x * HD + tid] = acc;
}

// ---------------- decoder BN stats via topic histogram ----------------
__global__ __launch_bounds__(128) void k_decstats(const float* __restrict__ G,
                                                  const float* __restrict__ BE) {
    __shared__ float cnt[KC];
    int tid = threadIdx.x;
#pragma unroll
    for (int i = 0; i < 8; i++) cnt[tid + i * 128] = (float)g_count[tid + i * 128];
    __syncthreads();
    float s = 0.f, sq = 0.f;
    for (int k = 0; k < KC; k++) {
        float v = g_cbproj[k * HD + tid];
        float c = cnt[k];
        s += c * v;
        sq += c * v * v;
    }
    float mean = s * (1.f / (float)NR);
    float var  = sq * (1.f / (float)NR) - mean * mean;
    float sc = G[tid] * rsqrtf(var + EPSBN);
    g_dscale[tid] = sc;
    g_dshift[tid] = BE[tid] - mean * sc;
}

// ---------------- decoded = relu(bn(cbproj)) @ dec_w2 + b2  [1024,512] -----
__global__ __launch_bounds__(256) void k_decoded(const float* __restrict__ W2,
                                                 const float* __restrict__ B2) {
    __shared__ float as[16][HD];
    int tid = threadIdx.x;
    int k0 = blockIdx.x * 16;
#pragma unroll
    for (int i = 0; i < 8; i++) {
        int idx = tid + i * 256;
        int r = idx >> 7, j = idx & 127;
        float v = g_cbproj[(k0 + r) * HD + j];
        as[r][j] = fmaxf(fmaf(v, g_dscale[j], g_dshift[j]), 0.f);
    }
    __syncthreads();
    float acc0[16] = {}, acc1[16] = {};
    int c0 = tid, c1 = tid + 256;
    for (int j = 0; j < HD; j++) {
        float w0 = W2[j * DIN + c0];
        float w1 = W2[j * DIN + c1];
#pragma unroll
        for (int r = 0; r < 16; r++) {
            float a = as[r][j];
            acc0[r] = fmaf(a, w0, acc0[r]);
            acc1[r] = fmaf(a, w1, acc1[r]);
        }
    }
    float b0 = B2[c0], b1 = B2[c1];
#pragma unroll
    for (int r = 0; r < 16; r++) {
        g_decoded[(k0 + r) * DIN + c0] = acc0[r] + b0;
        g_decoded[(k0 + r) * DIN + c1] = acc1[r] + b1;
    }
}

// ---------------- recon: sum over all elements of (decoded[topic]-X)^2 -----
__global__ __launch_bounds__(256) void k_recon(const float* __restrict__ X) {
    int warp = threadIdx.x >> 5, lane = threadIdx.x & 31;
    float lsum = 0.f;
    int row0 = blockIdx.x * 128 + warp * 16;
    for (int rr = 0; rr < 16; rr++) {
        int row = row0 + rr;
        int t = g_topic[row];
        const float4* xr = (const float4*)X + row * 128;
        const float4* dr = (const float4*)g_decoded + t * 128;
#pragma unroll
        for (int i = 0; i < 4; i++) {
            float4 a = xr[lane + i * 32];
            float4 b = dr[lane + i * 32];
            float dx = a.x - b.x, dy = a.y - b.y, dz = a.z - b.z, dw = a.w - b.w;
            lsum += dx * dx + dy * dy + dz * dz + dw * dw;
        }
    }
#pragma unroll
    for (int off = 16; off; off >>= 1) lsum += __shfl_xor_sync(0xffffffffu, lsum, off);
    if (lane == 0) atomicAdd(&g_recon, lsum);
}

// ---------------- final scalar: 2*zloss + sqrt(recon) ----------------
__global__ void k_final(float* __restrict__ out) {
    out[0] = 2.f * g_zloss + sqrtf(g_recon);
}

// ---------------- launcher ----------------
extern "C" void kernel_launch(void* const* d_in, const int* in_sizes, int n_in,
                              void* d_out, int out_size) {
    const float* X    = (const float*)d_in[0];
    const float* ew1  = (const float*)d_in[1];
    const float* eb1  = (const float*)d_in[2];
    const float* eg1  = (const float*)d_in[3];
    const float* ebe1 = (const float*)d_in[4];
    const float* ew2  = (const float*)d_in[5];
    const float* eb2  = (const float*)d_in[6];
    const float* dw1  = (const float*)d_in[7];
    const float* db1  = (const float*)d_in[8];
    const float* dg1  = (const float*)d_in[9];
    const float* dbe1 = (const float*)d_in[10];
    const float* dw2  = (const float*)d_in[11];
    const float* db2  = (const float*)d_in[12];
    const float* cb   = (const float*)d_in[13];

    cudaFuncSetAttribute(k_dist, cudaFuncAttributeMaxDynamicSharedMemorySize,
                         (KC * DD + KC) * (int)sizeof(float));

    k_init<<<4, 256>>>();
    k_gemm1<<<NR / 128, 256>>>(X, ew1, eb1);
    k_colstats<<<NR / 256, 128>>>();
    k_bnfin<<<1, 128>>>(eg1, ebe1);
    k_gemm2<<<NR / 256, 256>>>(ew2, eb2);
    k_cbnorm<<<KC / 256, 256>>>(cb);
    k_dist<<<NR / 512, 512, (KC * DD + KC) * (int)sizeof(float)>>>(cb);
    k_cbproj<<<KC, 128>>>(cb, dw1, db1);
    k_decstats<<<1, 128>>>(dg1, dbe1);
    k_decoded<<<KC / 16, 256>>>(dw2, db2);
    k_recon<<<NR / 128, 256>>>(X);
    k_final<<<1, 1>>>((float*)d_out);
}

// round 3
// speedup vs baseline: 1.4981x; 1.4981x over previous
#include <cuda_runtime.h>
#include <math.h>

// Problem sizes (fixed)
#define NR   65536
#define DIN  512
#define HD   128
#define DD   32
#define KC   1024
#define EPSBN 1e-5f

// ---------------- scratch (device globals; no allocations) ----------------
__device__ float g_h1[NR * HD];        // encoder hidden pre-BN   (33.5 MB)
__device__ float g_z[NR * DD];         // encoder output          (8 MB)
__device__ int   g_topic[NR];
__device__ float g_colsum[HD];
__device__ float g_colsumsq[HD];
__device__ float g_escale[HD];         // gamma * rstd
__device__ float g_eshift[HD];         // beta - mean*scale
__device__ float g_cbnorm[KC];
__device__ float g_cbproj[KC * HD];    // codebook @ dec_w1 + dec_b1
__device__ int   g_count[KC];
__device__ float g_dscale[HD];
__device__ float g_dshift[HD];
__device__ float g_decoded[KC * DIN];  // decoded codewords (2 MB)
__device__ float g_zloss;
__device__ float g_recon;

// ---------------- tf32 helpers ----------------
__device__ __forceinline__ unsigned f2tf(float f) {
    unsigned r;
    asm("cvt.rna.tf32.f32 %0, %1;" : "=r"(r) : "f"(f));
    return r;
}

__device__ __forceinline__ void mma_tf32(float& c0, float& c1, float& c2, float& c3,
                                         unsigned a0, unsigned a1, unsigned a2, unsigned a3,
                                         unsigned b0, unsigned b1) {
    asm volatile(
        "mma.sync.aligned.m16n8k8.row.col.f32.tf32.tf32.f32 "
        "{%0,%1,%2,%3},{%4,%5,%6,%7},{%8,%9},{%0,%1,%2,%3};"
        : "+f"(c0), "+f"(c1), "+f"(c2), "+f"(c3)
        : "r"(a0), "r"(a1), "r"(a2), "r"(a3), "r"(b0), "r"(b1));
}

// ---------------- init: zero accumulators every call ----------------
__global__ void k_init() {
    int t = blockIdx.x * blockDim.x + threadIdx.x;
    if (t < HD) { g_colsum[t] = 0.f; g_colsumsq[t] = 0.f; }
    if (t < KC) g_count[t] = 0;
    if (t == 0) { g_zloss = 0.f; g_recon = 0.f; }
}

// ---------------- GEMM1 (tf32 mma): h1 = X[65536,512] @ W[512,128] + b -----
// block tile 128m x 128n, K chunks of 32; 8 warps = 4m x 2n, warp 32m x 64n.
// smem padded stride 36: fragment banks = (4*row + k) % 32 -> conflict-free.
__global__ __launch_bounds__(256, 2) void k_gemm1(const float* __restrict__ X,
                                                  const float* __restrict__ W,
                                                  const float* __restrict__ Bb) {
    __shared__ unsigned xs[128 * 36];   // [m][k] tf32 bits
    __shared__ unsigned wts[128 * 36];  // [n][k] tf32 bits (transposed W)
    int tid = threadIdx.x, lane = tid & 31, warp = tid >> 5;
    int row0 = blockIdx.x * 128;
    int m0 = (warp >> 1) * 32;
    int n0w = (warp & 1) * 64;

    float c[2][8][4];
#pragma unroll
    for (int i = 0; i < 2; i++)
#pragma unroll
        for (int j = 0; j < 8; j++)
#pragma unroll
            for (int q = 0; q < 4; q++) c[i][j][q] = 0.f;

    int xr = tid >> 1, xk = (tid & 1) * 16;
    const float* Xp = X + (row0 + xr) * DIN + xk;
    int wn = tid & 127, wk0 = (tid >> 7) * 4;

    for (int kk = 0; kk < DIN; kk += 32) {
        float4 xv[4];
#pragma unroll
        for (int i = 0; i < 4; i++) xv[i] = *(const float4*)(Xp + kk + 4 * i);
        float wv[16];
#pragma unroll
        for (int j = 0; j < 4; j++)
#pragma unroll
            for (int q = 0; q < 4; q++)
                wv[j * 4 + q] = W[(kk + wk0 + 8 * j + q) * HD + wn];

        __syncthreads();
#pragma unroll
        for (int i = 0; i < 4; i++) {
            uint4 u;
            u.x = f2tf(xv[i].x); u.y = f2tf(xv[i].y);
            u.z = f2tf(xv[i].z); u.w = f2tf(xv[i].w);
            *(uint4*)&xs[xr * 36 + xk + 4 * i] = u;
        }
#pragma unroll
        for (int j = 0; j < 4; j++) {
            uint4 u;
            u.x = f2tf(wv[j * 4 + 0]); u.y = f2tf(wv[j * 4 + 1]);
            u.z = f2tf(wv[j * 4 + 2]); u.w = f2tf(wv[j * 4 + 3]);
            *(uint4*)&wts[wn * 36 + wk0 + 8 * j] = u;
        }
        __syncthreads();

#pragma unroll
        for (int s = 0; s < 4; s++) {
            int kb = 8 * s + (lane & 3);
            unsigned a[2][4];
#pragma unroll
            for (int mt = 0; mt < 2; mt++) {
                int mr = m0 + mt * 16 + (lane >> 2);
                a[mt][0] = xs[mr * 36 + kb];
                a[mt][1] = xs[(mr + 8) * 36 + kb];
                a[mt][2] = xs[mr * 36 + kb + 4];
                a[mt][3] = xs[(mr + 8) * 36 + kb + 4];
            }
#pragma unroll
            for (int nt = 0; nt < 8; nt++) {
                int nc = n0w + nt * 8 + (lane >> 2);
                unsigned b0 = wts[nc * 36 + kb];
                unsigned b1 = wts[nc * 36 + kb + 4];
                mma_tf32(c[0][nt][0], c[0][nt][1], c[0][nt][2], c[0][nt][3],
                         a[0][0], a[0][1], a[0][2], a[0][3], b0, b1);
                mma_tf32(c[1][nt][0], c[1][nt][1], c[1][nt][2], c[1][nt][3],
                         a[1][0], a[1][1], a[1][2], a[1][3], b0, b1);
            }
        }
    }
    // epilogue: add bias, store
#pragma unroll
    for (int mt = 0; mt < 2; mt++) {
        int r = row0 + m0 + mt * 16 + (lane >> 2);
#pragma unroll
        for (int nt = 0; nt < 8; nt++) {
            int col = n0w + nt * 8 + 2 * (lane & 3);
            float b0v = Bb[col], b1v = Bb[col + 1];
            *(float2*)&g_h1[r * HD + col] =
                make_float2(c[mt][nt][0] + b0v, c[mt][nt][1] + b1v);
            *(float2*)&g_h1[(r + 8) * HD + col] =
                make_float2(c[mt][nt][2] + b0v, c[mt][nt][3] + b1v);
        }
    }
}

// ---------------- per-column sum / sumsq over h1 ----------------
__global__ __launch_bounds__(128) void k_colstats() {
    int j = threadIdx.x;
    int base = blockIdx.x * 256 * HD;
    float s = 0.f, sq = 0.f;
#pragma unroll 4
    for (int r = 0; r < 256; r++) {
        float v = g_h1[base + r * HD + j];
        s += v;
        sq += v * v;
    }
    atomicAdd(&g_colsum[j], s);
    atomicAdd(&g_colsumsq[j], sq);
}

__global__ void k_bnfin(const float* __restrict__ G, const float* __restrict__ BE) {
    int j = threadIdx.x;
    float mean = g_colsum[j] * (1.f / (float)NR);
    float var  = g_colsumsq[j] * (1.f / (float)NR) - mean * mean;
    float sc = G[j] * rsqrtf(var + EPSBN);
    g_escale[j] = sc;
    g_eshift[j] = BE[j] - mean * sc;
}

// ---------------- GEMM2 (tf32 mma): z = relu(bn(h1)) @ W2[128,32] + b2 -----
// block 128 rows, 8 warps x 16 rows; BN+ReLU fused into smem staging.
__global__ __launch_bounds__(256) void k_gemm2(const float* __restrict__ W2,
                                               const float* __restrict__ B2) {
    extern __shared__ unsigned gsm[];
    unsigned* xs = gsm;                       // 128 x 68 (k-chunk 64, pad 4)
    unsigned* wt = gsm + 128 * 68;            // 32 x 132 (full K=128, pad 4)
    float* esc = (float*)(gsm + 128 * 68 + 32 * 132);
    float* esh = esc + 128;

    int tid = threadIdx.x, lane = tid & 31, warp = tid >> 5;
    int row0 = blockIdx.x * 128;

    if (tid < 128) { esc[tid] = g_escale[tid]; esh[tid] = g_eshift[tid]; }
#pragma unroll
    for (int i = 0; i < 16; i++) {
        int e = tid + i * 256;                // e = k*32 + n
        int k = e >> 5, n = e & 31;
        wt[n * 132 + k] = f2tf(W2[e]);
    }

    float c[4][4];
#pragma unroll
    for (int nt = 0; nt < 4; nt++)
#pragma unroll
        for (int q = 0; q < 4; q++) c[nt][q] = 0.f;

    for (int kc = 0; kc < HD; kc += 64) {
        __syncthreads();
#pragma unroll
        for (int i = 0; i < 8; i++) {
            int e = tid + i * 256;            // 2048 float4 slots
            int r = e >> 4, c4 = (e & 15) * 4;
            int kg = kc + c4;
            float4 v = *(const float4*)&g_h1[(row0 + r) * HD + kg];
            uint4 u;
            u.x = f2tf(fmaxf(fmaf(v.x, esc[kg + 0], esh[kg + 0]), 0.f));
            u.y = f2tf(fmaxf(fmaf(v.y, esc[kg + 1], esh[kg + 1]), 0.f));
            u.z = f2tf(fmaxf(fmaf(v.z, esc[kg + 2], esh[kg + 2]), 0.f));
            u.w = f2tf(fmaxf(fmaf(v.w, esc[kg + 3], esh[kg + 3]), 0.f));
            *(uint4*)&xs[r * 68 + c4] = u;
        }
        __syncthreads();

#pragma unroll
        for (int s = 0; s < 8; s++) {
            int kb = 8 * s + (lane & 3);
            int mr = warp * 16 + (lane >> 2);
            unsigned a0 = xs[mr * 68 + kb];
            unsigned a1 = xs[(mr + 8) * 68 + kb];
            unsigned a2 = xs[mr * 68 + kb + 4];
            unsigned a3 = xs[(mr + 8) * 68 + kb + 4];
            int kg = kc + 8 * s + (lane & 3);
#pragma unroll
            for (int nt = 0; nt < 4; nt++) {
                int n = nt * 8 + (lane >> 2);
                unsigned b0 = wt[n * 132 + kg];
                unsigned b1 = wt[n * 132 + kg + 4];
                mma_tf32(c[nt][0], c[nt][1], c[nt][2], c[nt][3],
                         a0, a1, a2, a3, b0, b1);
            }
        }
    }
    int mr = row0 + warp * 16 + (lane >> 2);
#pragma unroll
    for (int nt = 0; nt < 4; nt++) {
        int col = nt * 8 + 2 * (lane & 3);
        float b0v = B2[col], b1v = B2[col + 1];
        *(float2*)&g_z[mr * DD + col] = make_float2(c[nt][0] + b0v, c[nt][1] + b1v);
        *(float2*)&g_z[(mr + 8) * DD + col] = make_float2(c[nt][2] + b0v, c[nt][3] + b1v);
    }
}

// ---------------- codebook squared norms ----------------
__global__ void k_cbnorm(const float* __restrict__ cb) {
    int k = blockIdx.x * 256 + threadIdx.x;
    const float4* c = (const float4*)(cb + k * DD);
    float s = 0.f;
#pragma unroll
    for (int i = 0; i < 8; i++) {
        float4 v = c[i];
        s += v.x * v.x + v.y * v.y + v.z * v.z + v.w * v.w;
    }
    g_cbnorm[k] = s;
}

// ---------------- distance (tf32 mma) + argmin + exact z_loss + histogram --
// block: 128 z-rows, 8 warps x 16 rows; codebook (tf32 bits) in dynamic smem.
__global__ __launch_bounds__(256) void k_dist(const float* __restrict__ cb) {
    extern __shared__ unsigned dsm[];
    unsigned* cbs = dsm;                       // 1024 x 36 tf32 bits
    float* zs  = (float*)(dsm + KC * 36);      // 128 x 36 fp32 (exact recompute)
    float* cns = zs + 128 * 36;                // 1024 fp32 norms

    int tid = threadIdx.x, lane = tid & 31, warp = tid >> 5;

    // stage codebook (tf32) -- 8192 float4 / 256 threads
#pragma unroll
    for (int i = 0; i < 32; i++) {
        int e = tid + i * 256;
        float4 v = ((const float4*)cb)[e];
        uint4 u;
        u.x = f2tf(v.x); u.y = f2tf(v.y); u.z = f2tf(v.z); u.w = f2tf(v.w);
        *(uint4*)&cbs[(e >> 3) * 36 + (e & 7) * 4] = u;
    }
    // stage z rows (fp32)
#pragma unroll
    for (int i = 0; i < 4; i++) {
        int r = tid >> 1, cc = (tid & 1) * 16 + 4 * i;
        float4 v = *(const float4*)&g_z[(blockIdx.x * 128 + r) * DD + cc];
        *(float4*)&zs[r * 36 + cc] = v;
    }
#pragma unroll
    for (int i = 0; i < 4; i++) cns[tid + i * 256] = g_cbnorm[tid + i * 256];
    __syncthreads();

    int m0 = warp * 16;
    int mr = m0 + (lane >> 2);
    unsigned a[4][4];
#pragma unroll
    for (int s = 0; s < 4; s++) {
        int kb = 8 * s + (lane & 3);
        a[s][0] = f2tf(zs[mr * 36 + kb]);
        a[s][1] = f2tf(zs[(mr + 8) * 36 + kb]);
        a[s][2] = f2tf(zs[mr * 36 + kb + 4]);
        a[s][3] = f2tf(zs[(mr + 8) * 36 + kb + 4]);
    }

    float bd0 = 3.4e38f, bdh = 3.4e38f;
    int bi0 = 0, bih = 0;
    for (int n0 = 0; n0 < KC / 8; n0++) {
        float c0 = 0.f, c1 = 0.f, c2 = 0.f, c3 = 0.f;
        int nb = (n0 * 8 + (lane >> 2)) * 36 + (lane & 3);
#pragma unroll
        for (int s = 0; s < 4; s++) {
            unsigned b0 = cbs[nb + 8 * s];
            unsigned b1 = cbs[nb + 8 * s + 4];
            mma_tf32(c0, c1, c2, c3, a[s][0], a[s][1], a[s][2], a[s][3], b0, b1);
        }
        int col0 = n0 * 8 + 2 * (lane & 3);
        float cn0 = cns[col0], cn1 = cns[col0 + 1];
        float d0 = fmaf(c0, -2.f, cn0), d1 = fmaf(c1, -2.f, cn1);
        float e0 = fmaf(c2, -2.f, cn0), e1 = fmaf(c3, -2.f, cn1);
        if (d0 < bd0) { bd0 = d0; bi0 = col0; }
        if (d1 < bd0) { bd0 = d1; bi0 = col0 + 1; }
        if (e0 < bdh) { bdh = e0; bih = col0; }
        if (e1 < bdh) { bdh = e1; bih = col0 + 1; }
    }
    // reduce (min, first-index) across the 4 lanes of each quad
#pragma unroll
    for (int off = 1; off <= 2; off <<= 1) {
        float od = __shfl_xor_sync(0xffffffffu, bd0, off);
        int   oi = __shfl_xor_sync(0xffffffffu, bi0, off);
        if (od < bd0 || (od == bd0 && oi < bi0)) { bd0 = od; bi0 = oi; }
        od = __shfl_xor_sync(0xffffffffu, bdh, off);
        oi = __shfl_xor_sync(0xffffffffu, bih, off);
        if (od < bdh || (od == bdh && oi < bih)) { bdh = od; bih = oi; }
    }

    float lsum = 0.f;
    if ((lane & 3) == 0) {
        int rl = m0 + (lane >> 2);
        int grow = blockIdx.x * 128 + rl;
        // exact fp32 recompute of the winning distances
        float zn0 = 0.f, dt0 = 0.f, zn1 = 0.f, dt1 = 0.f;
        const float* cb0 = cb + bi0 * DD;
        const float* cb1 = cb + bih * DD;
#pragma unroll
        for (int k = 0; k < DD; k++) {
            float z0 = zs[rl * 36 + k];
            float z1 = zs[(rl + 8) * 36 + k];
            zn0 += z0 * z0; dt0 = fmaf(z0, cb0[k], dt0);
            zn1 += z1 * z1; dt1 = fmaf(z1, cb1[k], dt1);
        }
        lsum = (zn0 + g_cbnorm[bi0] - 2.f * dt0) + (zn1 + g_cbnorm[bih] - 2.f * dt1);
        g_topic[grow] = bi0;
        g_topic[grow + 8] = bih;
        atomicAdd(&g_count[bi0], 1);
        atomicAdd(&g_count[bih], 1);
    }
#pragma unroll
    for (int off = 16; off; off >>= 1) lsum += __shfl_xor_sync(0xffffffffu, lsum, off);
    if (lane == 0) atomicAdd(&g_zloss, lsum);
}

// ---------------- cbproj = codebook @ dec_w1 + dec_b1  [1024,128] ----------
__global__ __launch_bounds__(128) void k_cbproj(const float* __restrict__ cb,
                                                const float* __restrict__ W1,
                                                const float* __restrict__ B1) {
    __shared__ float row[DD];
    int tid = threadIdx.x;
    if (tid < 8) ((float4*)row)[tid] = ((const float4*)cb)[blockIdx.x * 8 + tid];
    __syncthreads();
    float acc = B1[tid];
#pragma unroll
    for (int d = 0; d < DD; d++) acc = fmaf(row[d], W1[d * HD + tid], acc);
    g_cbproj[blockIdx.x * HD + tid] = acc;
}

// ---------------- decoder BN stats via topic histogram ----------------
__global__ __launch_bounds__(128) void k_decstats(const float* __restrict__ G,
                                                  const float* __restrict__ BE) {
    __shared__ float cnt[KC];
    int tid = threadIdx.x;
#pragma unroll
    for (int i = 0; i < 8; i++) cnt[tid + i * 128] = (float)g_count[tid + i * 128];
    __syncthreads();
    float s = 0.f, sq = 0.f;
    for (int k = 0; k < KC; k++) {
        float v = g_cbproj[k * HD + tid];
        float c = cnt[k];
        s += c * v;
        sq += c * v * v;
    }
    float mean = s * (1.f / (float)NR);
    float var  = sq * (1.f / (float)NR) - mean * mean;
    float sc = G[tid] * rsqrtf(var + EPSBN);
    g_dscale[tid] = sc;
    g_dshift[tid] = BE[tid] - mean * sc;
}

// ---------------- decoded = relu(bn(cbproj)) @ dec_w2 + b2  [1024,512] -----
__global__ __launch_bounds__(256) void k_decoded(const float* __restrict__ W2,
                                                 const float* __restrict__ B2) {
    __shared__ float as[16][HD];
    int tid = threadIdx.x;
    int k0 = blockIdx.x * 16;
#pragma unroll
    for (int i = 0; i < 8; i++) {
        int idx = tid + i * 256;
        int r = idx >> 7, j = idx & 127;
        float v = g_cbproj[(k0 + r) * HD + j];
        as[r][j] = fmaxf(fmaf(v, g_dscale[j], g_dshift[j]), 0.f);
    }
    __syncthreads();
    float acc0[16] = {}, acc1[16] = {};
    int c0 = tid, c1 = tid + 256;
    for (int j = 0; j < HD; j++) {
        float w0 = W2[j * DIN + c0];
        float w1 = W2[j * DIN + c1];
#pragma unroll
        for (int r = 0; r < 16; r++) {
            float a = as[r][j];
            acc0[r] = fmaf(a, w0, acc0[r]);
            acc1[r] = fmaf(a, w1, acc1[r]);
        }
    }
    float b0 = B2[c0], b1 = B2[c1];
#pragma unroll
    for (int r = 0; r < 16; r++) {
        g_decoded[(k0 + r) * DIN + c0] = acc0[r] + b0;
        g_decoded[(k0 + r) * DIN + c1] = acc1[r] + b1;
    }
}

// ---------------- recon: sum over all elements of (decoded[topic]-X)^2 -----
__global__ __launch_bounds__(256) void k_recon(const float* __restrict__ X) {
    int warp = threadIdx.x >> 5, lane = threadIdx.x & 31;
    float lsum = 0.f;
    int row0 = blockIdx.x * 128 + warp * 16;
    for (int rr = 0; rr < 16; rr++) {
        int row = row0 + rr;
        int t = g_topic[row];
        const float4* xr = (const float4*)X + row * 128;
        const float4* dr = (const float4*)g_decoded + t * 128;
#pragma unroll
        for (int i = 0; i < 4; i++) {
            float4 a = xr[lane + i * 32];
            float4 b = dr[lane + i * 32];
            float dx = a.x - b.x, dy = a.y - b.y, dz = a.z - b.z, dw = a.w - b.w;
            lsum += dx * dx + dy * dy + dz * dz + dw * dw;
        }
    }
#pragma unroll
    for (int off = 16; off; off >>= 1) lsum += __shfl_xor_sync(0xffffffffu, lsum, off);
    if (lane == 0) atomicAdd(&g_recon, lsum);
}

// ---------------- final scalar: 2*zloss + sqrt(recon) ----------------
__global__ void k_final(float* __restrict__ out) {
    out[0] = 2.f * g_zloss + sqrtf(g_recon);
}

// ---------------- launcher ----------------
extern "C" void kernel_launch(void* const* d_in, const int* in_sizes, int n_in,
                              void* d_out, int out_size) {
    const float* X    = (const float*)d_in[0];
    const float* ew1  = (const float*)d_in[1];
    const float* eb1  = (const float*)d_in[2];
    const float* eg1  = (const float*)d_in[3];
    const float* ebe1 = (const float*)d_in[4];
    const float* ew2  = (const float*)d_in[5];
    const float* eb2  = (const float*)d_in[6];
    const float* dw1  = (const float*)d_in[7];
    const float* db1  = (const float*)d_in[8];
    const float* dg1  = (const float*)d_in[9];
    const float* dbe1 = (const float*)d_in[10];
    const float* dw2  = (const float*)d_in[11];
    const float* db2  = (const float*)d_in[12];
    const float* cb   = (const float*)d_in[13];

    const int distSmem  = (KC * 36 + 128 * 36 + KC) * (int)sizeof(float);
    const int gemm2Smem = (128 * 68 + 32 * 132 + 256) * (int)sizeof(float);
    cudaFuncSetAttribute(k_dist, cudaFuncAttributeMaxDynamicSharedMemorySize, distSmem);
    cudaFuncSetAttribute(k_gemm2, cudaFuncAttributeMaxDynamicSharedMemorySize, gemm2Smem);

    k_init<<<4, 256>>>();
    k_gemm1<<<NR / 128, 256>>>(X, ew1, eb1);
    k_colstats<<<NR / 256, 128>>>();
    k_bnfin<<<1, 128>>>(eg1, ebe1);
    k_gemm2<<<NR / 128, 256, gemm2Smem>>>(ew2, eb2);
    k_cbnorm<<<KC / 256, 256>>>(cb);
    k_dist<<<NR / 128, 256, distSmem>>>(cb);
    k_cbproj<<<KC, 128>>>(cb, dw1, db1);
    k_decstats<<<1, 128>>>(dg1, dbe1);
    k_decoded<<<KC / 16, 256>>>(dw2, db2);
    k_recon<<<NR / 128, 256>>>(X);
    k_final<<<1, 1>>>((float*)d_out);
}

// round 4
// speedup vs baseline: 1.9911x; 1.3290x over previous
#include <cuda_runtime.h>
#include <math.h>

// Problem sizes (fixed)
#define NR   65536
#define DIN  512
#define HD   128
#define DD   32
#define KC   1024
#define EPSBN 1e-5f

// ---------------- scratch (device globals; no allocations) ----------------
__device__ float    g_h1[NR * HD];       // encoder hidden pre-BN (33.5 MB)
__device__ float    g_z[NR * DD];        // encoder output (8 MB)
__device__ int      g_topic[NR];
__device__ float    g_colsum[HD];
__device__ float    g_colsumsq[HD];
__device__ float    g_escale[HD];
__device__ float    g_eshift[HD];
__device__ float    g_cbnorm[KC];
__device__ unsigned g_cbtf[KC * DD];     // codebook pre-converted to tf32 bits
__device__ float    g_cbproj[KC * HD];   // codebook @ dec_w1 + dec_b1
__device__ int      g_count[KC];
__device__ float    g_dscale[HD];
__device__ float    g_dshift[HD];
__device__ float    g_decoded[KC * DIN]; // decoded codewords (2 MB)
__device__ float    g_zloss;
__device__ float    g_recon;

// ---------------- tf32 helpers ----------------
__device__ __forceinline__ unsigned f2tf(float f) {
    unsigned r;
    asm("cvt.rna.tf32.f32 %0, %1;" : "=r"(r) : "f"(f));
    return r;
}

__device__ __forceinline__ void mma_tf32(float& c0, float& c1, float& c2, float& c3,
                                         unsigned a0, unsigned a1, unsigned a2, unsigned a3,
                                         unsigned b0, unsigned b1) {
    asm volatile(
        "mma.sync.aligned.m16n8k8.row.col.f32.tf32.tf32.f32 "
        "{%0,%1,%2,%3},{%4,%5,%6,%7},{%8,%9},{%0,%1,%2,%3};"
        : "+f"(c0), "+f"(c1), "+f"(c2), "+f"(c3)
        : "r"(a0), "r"(a1), "r"(a2), "r"(a3), "r"(b0), "r"(b1));
}

// ---------------- init: zero accumulators every call ----------------
__global__ void k_init() {
    int t = blockIdx.x * blockDim.x + threadIdx.x;
    if (t < HD) { g_colsum[t] = 0.f; g_colsumsq[t] = 0.f; }
    if (t < KC) g_count[t] = 0;
    if (t == 0) { g_zloss = 0.f; g_recon = 0.f; }
}

// ------------- cbprep: norms + tf32 convert + cbproj (1 kernel) -----------
// one block per codebook row
__global__ __launch_bounds__(128) void k_cbprep(const float* __restrict__ cb,
                                                const float* __restrict__ W1,
                                                const float* __restrict__ B1) {
    __shared__ float row[DD];
    int tid = threadIdx.x, k = blockIdx.x;
    if (tid < 8) ((float4*)row)[tid] = ((const float4*)cb)[k * 8 + tid];
    __syncthreads();
    if (tid < 32) {
        float v = row[tid];
        g_cbtf[k * DD + tid] = f2tf(v);
        float s = v * v;
#pragma unroll
        for (int off = 16; off; off >>= 1) s += __shfl_xor_sync(0xffffffffu, s, off);
        if (tid == 0) g_cbnorm[k] = s;
    }
    float acc = B1[tid];
#pragma unroll
    for (int d = 0; d < DD; d++) acc = fmaf(row[d], W1[d * HD + tid], acc);
    g_cbproj[k * HD + tid] = acc;
}

// ------- GEMM1 (tf32 mma) + fused column stats: h1 = X@W + b --------------
// block tile 128m x 128n, K chunks of 32; 8 warps = 4m x 2n, warp 32m x 64n.
// register prefetch of next chunk; stats reduced in smem then one atomic/col.
__global__ __launch_bounds__(256, 2) void k_gemm1(const float* __restrict__ X,
                                                  const float* __restrict__ W,
                                                  const float* __restrict__ Bb) {
    __shared__ unsigned xs[128 * 36];   // [m][k] tf32 bits
    __shared__ unsigned wts[128 * 36];  // [n][k] tf32 bits (transposed W)
    __shared__ float ss[HD], ssq[HD];
    int tid = threadIdx.x, lane = tid & 31, warp = tid >> 5;
    int row0 = blockIdx.x * 128;
    int m0 = (warp >> 1) * 32;
    int n0w = (warp & 1) * 64;

    if (tid < HD) { ss[tid] = 0.f; ssq[tid] = 0.f; }

    float c[2][8][4];
#pragma unroll
    for (int i = 0; i < 2; i++)
#pragma unroll
        for (int j = 0; j < 8; j++)
#pragma unroll
            for (int q = 0; q < 4; q++) c[i][j][q] = 0.f;

    int xr = tid >> 1, xk = (tid & 1) * 16;
    const float* Xp = X + (row0 + xr) * DIN + xk;
    int wn = tid & 127, wk0 = (tid >> 7) * 4;

    // prefetch chunk 0
    float4 xv[4];
    float wv[16];
#pragma unroll
    for (int i = 0; i < 4; i++) xv[i] = *(const float4*)(Xp + 4 * i);
#pragma unroll
    for (int j = 0; j < 4; j++)
#pragma unroll
        for (int q = 0; q < 4; q++)
            wv[j * 4 + q] = W[(wk0 + 8 * j + q) * HD + wn];

    for (int kk = 0; kk < DIN; kk += 32) {
        __syncthreads();
#pragma unroll
        for (int i = 0; i < 4; i++) {
            uint4 u;
            u.x = f2tf(xv[i].x); u.y = f2tf(xv[i].y);
            u.z = f2tf(xv[i].z); u.w = f2tf(xv[i].w);
            *(uint4*)&xs[xr * 36 + xk + 4 * i] = u;
        }
#pragma unroll
        for (int j = 0; j < 4; j++) {
            uint4 u;
            u.x = f2tf(wv[j * 4 + 0]); u.y = f2tf(wv[j * 4 + 1]);
            u.z = f2tf(wv[j * 4 + 2]); u.w = f2tf(wv[j * 4 + 3]);
            *(uint4*)&wts[wn * 36 + wk0 + 8 * j] = u;
        }
        __syncthreads();

        // issue next chunk's global loads before the MMA block (latency hiding)
        if (kk + 32 < DIN) {
#pragma unroll
            for (int i = 0; i < 4; i++) xv[i] = *(const float4*)(Xp + kk + 32 + 4 * i);
#pragma unroll
            for (int j = 0; j < 4; j++)
#pragma unroll
                for (int q = 0; q < 4; q++)
                    wv[j * 4 + q] = W[(kk + 32 + wk0 + 8 * j + q) * HD + wn];
        }

#pragma unroll
        for (int s = 0; s < 4; s++) {
            int kb = 8 * s + (lane & 3);
            unsigned a[2][4];
#pragma unroll
            for (int mt = 0; mt < 2; mt++) {
                int mr = m0 + mt * 16 + (lane >> 2);
                a[mt][0] = xs[mr * 36 + kb];
                a[mt][1] = xs[(mr + 8) * 36 + kb];
                a[mt][2] = xs[mr * 36 + kb + 4];
                a[mt][3] = xs[(mr + 8) * 36 + kb + 4];
            }
#pragma unroll
            for (int nt = 0; nt < 8; nt++) {
                int nc = n0w + nt * 8 + (lane >> 2);
                unsigned b0 = wts[nc * 36 + kb];
                unsigned b1 = wts[nc * 36 + kb + 4];
                mma_tf32(c[0][nt][0], c[0][nt][1], c[0][nt][2], c[0][nt][3],
                         a[0][0], a[0][1], a[0][2], a[0][3], b0, b1);
                mma_tf32(c[1][nt][0], c[1][nt][1], c[1][nt][2], c[1][nt][3],
                         a[1][0], a[1][1], a[1][2], a[1][3], b0, b1);
            }
        }
    }

    // epilogue: bias, store h1, accumulate column stats
    int r0 = row0 + m0 + (lane >> 2);
#pragma unroll
    for (int nt = 0; nt < 8; nt++) {
        int col = n0w + nt * 8 + 2 * (lane & 3);
        float b0v = Bb[col], b1v = Bb[col + 1];
        float v00 = c[0][nt][0] + b0v, v01 = c[0][nt][1] + b1v;
        float v02 = c[0][nt][2] + b0v, v03 = c[0][nt][3] + b1v;
        float v10 = c[1][nt][0] + b0v, v11 = c[1][nt][1] + b1v;
        float v12 = c[1][nt][2] + b0v, v13 = c[1][nt][3] + b1v;
        *(float2*)&g_h1[r0 * HD + col]        = make_float2(v00, v01);
        *(float2*)&g_h1[(r0 + 8) * HD + col]  = make_float2(v02, v03);
        *(float2*)&g_h1[(r0 + 16) * HD + col] = make_float2(v10, v11);
        *(float2*)&g_h1[(r0 + 24) * HD + col] = make_float2(v12, v13);
        atomicAdd(&ss[col],      v00 + v02 + v10 + v12);
        atomicAdd(&ss[col + 1],  v01 + v03 + v11 + v13);
        atomicAdd(&ssq[col],     v00 * v00 + v02 * v02 + v10 * v10 + v12 * v12);
        atomicAdd(&ssq[col + 1], v01 * v01 + v03 * v03 + v11 * v11 + v13 * v13);
    }
    __syncthreads();
    if (tid < HD) {
        atomicAdd(&g_colsum[tid], ss[tid]);
        atomicAdd(&g_colsumsq[tid], ssq[tid]);
    }
}

__global__ void k_bnfin(const float* __restrict__ G, const float* __restrict__ BE) {
    int j = threadIdx.x;
    float mean = g_colsum[j] * (1.f / (float)NR);
    float var  = g_colsumsq[j] * (1.f / (float)NR) - mean * mean;
    float sc = G[j] * rsqrtf(var + EPSBN);
    g_escale[j] = sc;
    g_eshift[j] = BE[j] - mean * sc;
}

// ---------------- GEMM2 (tf32 mma): z = relu(bn(h1)) @ W2[128,32] + b2 -----
__global__ __launch_bounds__(256) void k_gemm2(const float* __restrict__ W2,
                                               const float* __restrict__ B2) {
    extern __shared__ unsigned gsm[];
    unsigned* xs = gsm;                       // 128 x 68
    unsigned* wt = gsm + 128 * 68;            // 32 x 132
    float* esc = (float*)(gsm + 128 * 68 + 32 * 132);
    float* esh = esc + 128;

    int tid = threadIdx.x, lane = tid & 31, warp = tid >> 5;
    int row0 = blockIdx.x * 128;

    if (tid < 128) { esc[tid] = g_escale[tid]; esh[tid] = g_eshift[tid]; }
#pragma unroll
    for (int i = 0; i < 16; i++) {
        int e = tid + i * 256;
        int k = e >> 5, n = e & 31;
        wt[n * 132 + k] = f2tf(W2[e]);
    }

    float c[4][4];
#pragma unroll
    for (int nt = 0; nt < 4; nt++)
#pragma unroll
        for (int q = 0; q < 4; q++) c[nt][q] = 0.f;

    for (int kc = 0; kc < HD; kc += 64) {
        __syncthreads();
#pragma unroll
        for (int i = 0; i < 8; i++) {
            int e = tid + i * 256;
            int r = e >> 4, c4 = (e & 15) * 4;
            int kg = kc + c4;
            float4 v = *(const float4*)&g_h1[(row0 + r) * HD + kg];
            uint4 u;
            u.x = f2tf(fmaxf(fmaf(v.x, esc[kg + 0], esh[kg + 0]), 0.f));
            u.y = f2tf(fmaxf(fmaf(v.y, esc[kg + 1], esh[kg + 1]), 0.f));
            u.z = f2tf(fmaxf(fmaf(v.z, esc[kg + 2], esh[kg + 2]), 0.f));
            u.w = f2tf(fmaxf(fmaf(v.w, esc[kg + 3], esh[kg + 3]), 0.f));
            *(uint4*)&xs[r * 68 + c4] = u;
        }
        __syncthreads();

#pragma unroll
        for (int s = 0; s < 8; s++) {
            int kb = 8 * s + (lane & 3);
            int mr = warp * 16 + (lane >> 2);
            unsigned a0 = xs[mr * 68 + kb];
            unsigned a1 = xs[(mr + 8) * 68 + kb];
            unsigned a2 = xs[mr * 68 + kb + 4];
            unsigned a3 = xs[(mr + 8) * 68 + kb + 4];
            int kg = kc + 8 * s + (lane & 3);
#pragma unroll
            for (int nt = 0; nt < 4; nt++) {
                int n = nt * 8 + (lane >> 2);
                unsigned b0 = wt[n * 132 + kg];
                unsigned b1 = wt[n * 132 + kg + 4];
                mma_tf32(c[nt][0], c[nt][1], c[nt][2], c[nt][3],
                         a0, a1, a2, a3, b0, b1);
            }
        }
    }
    int mr = row0 + warp * 16 + (lane >> 2);
#pragma unroll
    for (int nt = 0; nt < 4; nt++) {
        int col = nt * 8 + 2 * (lane & 3);
        float b0v = B2[col], b1v = B2[col + 1];
        *(float2*)&g_z[mr * DD + col] = make_float2(c[nt][0] + b0v, c[nt][1] + b1v);
        *(float2*)&g_z[(mr + 8) * DD + col] = make_float2(c[nt][2] + b0v, c[nt][3] + b1v);
    }
}

// ---------------- distance (tf32 mma) + argmin + exact z_loss + histogram --
// block: 256 z-rows, 16 warps x 16 rows; pre-converted codebook in smem.
__global__ __launch_bounds__(512) void k_dist(const float* __restrict__ cb) {
    extern __shared__ unsigned dsm[];
    unsigned* cbs = dsm;                       // 1024 x 36 tf32 bits
    float* zs  = (float*)(dsm + KC * 36);      // 256 x 36 fp32
    float* cns = zs + 256 * 36;                // 1024 fp32 norms

    int tid = threadIdx.x, lane = tid & 31, warp = tid >> 5;
    int row0 = blockIdx.x * 256;

    // stage codebook (already tf32): 8192 uint4 / 512 threads
#pragma unroll
    for (int i = 0; i < 16; i++) {
        int e = tid + i * 512;
        uint4 u = ((const uint4*)g_cbtf)[e];
        *(uint4*)&cbs[(e >> 3) * 36 + (e & 7) * 4] = u;
    }
    // stage z rows (fp32): 2048 float4
#pragma unroll
    for (int i = 0; i < 4; i++) {
        int e = tid + i * 512;
        int r = e >> 3, c4 = (e & 7) * 4;
        float4 v = ((const float4*)g_z)[(row0 + r) * 8 + (e & 7)];
        *(float4*)&zs[r * 36 + c4] = v;
    }
#pragma unroll
    for (int i = 0; i < 2; i++) cns[tid + i * 512] = g_cbnorm[tid + i * 512];
    __syncthreads();

    int m0 = warp * 16;
    int mr = m0 + (lane >> 2);
    unsigned a[4][4];
#pragma unroll
    for (int s = 0; s < 4; s++) {
        int kb = 8 * s + (lane & 3);
        a[s][0] = f2tf(zs[mr * 36 + kb]);
        a[s][1] = f2tf(zs[(mr + 8) * 36 + kb]);
        a[s][2] = f2tf(zs[mr * 36 + kb + 4]);
        a[s][3] = f2tf(zs[(mr + 8) * 36 + kb + 4]);
    }

    float bd0 = 3.4e38f, bdh = 3.4e38f;
    int bi0 = 0, bih = 0;
    for (int n0 = 0; n0 < KC / 8; n0++) {
        float c0 = 0.f, c1 = 0.f, c2 = 0.f, c3 = 0.f;
        int nb = (n0 * 8 + (lane >> 2)) * 36 + (lane & 3);
#pragma unroll
        for (int s = 0; s < 4; s++) {
            unsigned b0 = cbs[nb + 8 * s];
            unsigned b1 = cbs[nb + 8 * s + 4];
            mma_tf32(c0, c1, c2, c3, a[s][0], a[s][1], a[s][2], a[s][3], b0, b1);
        }
        int col0 = n0 * 8 + 2 * (lane & 3);
        float cn0 = cns[col0], cn1 = cns[col0 + 1];
        float d0 = fmaf(c0, -2.f, cn0), d1 = fmaf(c1, -2.f, cn1);
        float e0 = fmaf(c2, -2.f, cn0), e1 = fmaf(c3, -2.f, cn1);
        if (d0 < bd0) { bd0 = d0; bi0 = col0; }
        if (d1 < bd0) { bd0 = d1; bi0 = col0 + 1; }
        if (e0 < bdh) { bdh = e0; bih = col0; }
        if (e1 < bdh) { bdh = e1; bih = col0 + 1; }
    }
    // reduce (min, first-index) across the 4 lanes of each quad
#pragma unroll
    for (int off = 1; off <= 2; off <<= 1) {
        float od = __shfl_xor_sync(0xffffffffu, bd0, off);
        int   oi = __shfl_xor_sync(0xffffffffu, bi0, off);
        if (od < bd0 || (od == bd0 && oi < bi0)) { bd0 = od; bi0 = oi; }
        od = __shfl_xor_sync(0xffffffffu, bdh, off);
        oi = __shfl_xor_sync(0xffffffffu, bih, off);
        if (od < bdh || (od == bdh && oi < bih)) { bdh = od; bih = oi; }
    }

    float lsum = 0.f;
    if ((lane & 3) == 0) {
        int rl = m0 + (lane >> 2);
        int grow = row0 + rl;
        // exact fp32 recompute of the winning distances
        float zn0 = 0.f, dt0 = 0.f, zn1 = 0.f, dt1 = 0.f;
        const float* cb0 = cb + bi0 * DD;
        const float* cb1 = cb + bih * DD;
#pragma unroll
        for (int k = 0; k < DD; k++) {
            float z0 = zs[rl * 36 + k];
            float z1 = zs[(rl + 8) * 36 + k];
            zn0 += z0 * z0; dt0 = fmaf(z0, cb0[k], dt0);
            zn1 += z1 * z1; dt1 = fmaf(z1, cb1[k], dt1);
        }
        lsum = (zn0 + g_cbnorm[bi0] - 2.f * dt0) + (zn1 + g_cbnorm[bih] - 2.f * dt1);
        g_topic[grow] = bi0;
        g_topic[grow + 8] = bih;
        atomicAdd(&g_count[bi0], 1);
        atomicAdd(&g_count[bih], 1);
    }
#pragma unroll
    for (int off = 16; off; off >>= 1) lsum += __shfl_xor_sync(0xffffffffu, lsum, off);
    if (lane == 0) atomicAdd(&g_zloss, lsum);
}

// ---------------- decoder BN stats via topic histogram ----------------
__global__ __launch_bounds__(128) void k_decstats(const float* __restrict__ G,
                                                  const float* __restrict__ BE) {
    __shared__ float cnt[KC];
    int tid = threadIdx.x;
#pragma unroll
    for (int i = 0; i < 8; i++) cnt[tid + i * 128] = (float)g_count[tid + i * 128];
    __syncthreads();
    float s = 0.f, sq = 0.f;
    for (int k = 0; k < KC; k++) {
        float v = g_cbproj[k * HD + tid];
        float c = cnt[k];
        s += c * v;
        sq += c * v * v;
    }
    float mean = s * (1.f / (float)NR);
    float var  = sq * (1.f / (float)NR) - mean * mean;
    float sc = G[tid] * rsqrtf(var + EPSBN);
    g_dscale[tid] = sc;
    g_dshift[tid] = BE[tid] - mean * sc;
}

// ---------------- decoded = relu(bn(cbproj)) @ dec_w2 + b2  [1024,512] -----
__global__ __launch_bounds__(256) void k_decoded(const float* __restrict__ W2,
                                                 const float* __restrict__ B2) {
    __shared__ float as[16][HD];
    int tid = threadIdx.x;
    int k0 = blockIdx.x * 16;
#pragma unroll
    for (int i = 0; i < 8; i++) {
        int idx = tid + i * 256;
        int r = idx >> 7, j = idx & 127;
        float v = g_cbproj[(k0 + r) * HD + j];
        as[r][j] = fmaxf(fmaf(v, g_dscale[j], g_dshift[j]), 0.f);
    }
    __syncthreads();
    float acc0[16] = {}, acc1[16] = {};
    int c0 = tid, c1 = tid + 256;
    for (int j = 0; j < HD; j++) {
        float w0 = W2[j * DIN + c0];
        float w1 = W2[j * DIN + c1];
#pragma unroll
        for (int r = 0; r < 16; r++) {
            float a = as[r][j];
            acc0[r] = fmaf(a, w0, acc0[r]);
            acc1[r] = fmaf(a, w1, acc1[r]);
        }
    }
    float b0 = B2[c0], b1 = B2[c1];
#pragma unroll
    for (int r = 0; r < 16; r++) {
        g_decoded[(k0 + r) * DIN + c0] = acc0[r] + b0;
        g_decoded[(k0 + r) * DIN + c1] = acc1[r] + b1;
    }
}

// ---------------- recon: sum over all elements of (decoded[topic]-X)^2 -----
__global__ __launch_bounds__(256) void k_recon(const float* __restrict__ X) {
    int warp = threadIdx.x >> 5, lane = threadIdx.x & 31;
    float lsum = 0.f;
    int row0 = blockIdx.x * 128 + warp * 16;
    for (int rr = 0; rr < 16; rr++) {
        int row = row0 + rr;
        int t = g_topic[row];
        const float4* xr = (const float4*)X + row * 128;
        const float4* dr = (const float4*)g_decoded + t * 128;
#pragma unroll
        for (int i = 0; i < 4; i++) {
            float4 a = xr[lane + i * 32];
            float4 b = dr[lane + i * 32];
            float dx = a.x - b.x, dy = a.y - b.y, dz = a.z - b.z, dw = a.w - b.w;
            lsum += dx * dx + dy * dy + dz * dz + dw * dw;
        }
    }
#pragma unroll
    for (int off = 16; off; off >>= 1) lsum += __shfl_xor_sync(0xffffffffu, lsum, off);
    if (lane == 0) atomicAdd(&g_recon, lsum);
}

// ---------------- final scalar: 2*zloss + sqrt(recon) ----------------
__global__ void k_final(float* __restrict__ out) {
    out[0] = 2.f * g_zloss + sqrtf(g_recon);
}

// ---------------- launcher ----------------
extern "C" void kernel_launch(void* const* d_in, const int* in_sizes, int n_in,
                              void* d_out, int out_size) {
    const float* X    = (const float*)d_in[0];
    const float* ew1  = (const float*)d_in[1];
    const float* eb1  = (const float*)d_in[2];
    const float* eg1  = (const float*)d_in[3];
    const float* ebe1 = (const float*)d_in[4];
    const float* ew2  = (const float*)d_in[5];
    const float* eb2  = (const float*)d_in[6];
    const float* dw1  = (const float*)d_in[7];
    const float* db1  = (const float*)d_in[8];
    const float* dg1  = (const float*)d_in[9];
    const float* dbe1 = (const float*)d_in[10];
    const float* dw2  = (const float*)d_in[11];
    const float* db2  = (const float*)d_in[12];
    const float* cb   = (const float*)d_in[13];

    const int distSmem  = (KC * 36 + 256 * 36 + KC) * (int)sizeof(float);
    const int gemm2Smem = (128 * 68 + 32 * 132 + 256) * (int)sizeof(float);
    cudaFuncSetAttribute(k_dist, cudaFuncAttributeMaxDynamicSharedMemorySize, distSmem);
    cudaFuncSetAttribute(k_gemm2, cudaFuncAttributeMaxDynamicSharedMemorySize, gemm2Smem);

    k_init<<<4, 256>>>();
    k_cbprep<<<KC, 128>>>(cb, dw1, db1);
    k_gemm1<<<NR / 128, 256>>>(X, ew1, eb1);
    k_bnfin<<<1, 128>>>(eg1, ebe1);
    k_gemm2<<<NR / 128, 256, gemm2Smem>>>(ew2, eb2);
    k_dist<<<NR / 256, 512, distSmem>>>(cb);
    k_decstats<<<1, 128>>>(dg1, dbe1);
    k_decoded<<<KC / 16, 256>>>(dw2, db2);
    k_recon<<<NR / 128, 256>>>(X);
    k_final<<<1, 1>>>((float*)d_out);
}

// round 7
// speedup vs baseline: 2.3745x; 1.1926x over previous
#include <cuda_runtime.h>
#include <math.h>

// Problem sizes (fixed)
#define NR   65536
#define DIN  512
#define HD   128
#define DD   32
#define KC   1024
#define EPSBN 1e-5f

// ---------------- scratch (device globals; no allocations) ----------------
__device__ unsigned g_h1bf[NR * 64];     // encoder hidden pre-BN, bf16x2 (16.7 MB)
__device__ int      g_topic[NR];
__device__ float    g_colsum[HD];
__device__ float    g_colsumsq[HD];
__device__ float    g_escale[HD];
__device__ float    g_eshift[HD];
__device__ float    g_cbnorm[KC];
__device__ unsigned g_cbbf[KC * 16];     // codebook bf16x2 packed
__device__ float    g_cbproj[KC * HD];   // codebook @ dec_w1 + dec_b1
__device__ int      g_count[KC];
__device__ float    g_dscale[HD];
__device__ float    g_dshift[HD];
__device__ float    g_decoded[KC * DIN]; // decoded codewords (2 MB)
__device__ float    g_zloss;
__device__ float    g_recon;

// ---------------- bf16 helpers ----------------
__device__ __forceinline__ unsigned f2bf2(float lo, float hi) {
    unsigned r;
    asm("cvt.rn.bf16x2.f32 %0, %1, %2;" : "=r"(r) : "f"(hi), "f"(lo));
    return r;
}
__device__ __forceinline__ float bflo(unsigned u) { return __uint_as_float(u << 16); }
__device__ __forceinline__ float bfhi(unsigned u) { return __uint_as_float(u & 0xffff0000u); }

__device__ __forceinline__ void mma_bf16(float& c0, float& c1, float& c2, float& c3,
                                         unsigned a0, unsigned a1, unsigned a2, unsigned a3,
                                         unsigned b0, unsigned b1) {
    asm volatile(
        "mma.sync.aligned.m16n8k16.row.col.f32.bf16.bf16.f32 "
        "{%0,%1,%2,%3},{%4,%5,%6,%7},{%8,%9},{%0,%1,%2,%3};"
        : "+f"(c0), "+f"(c1), "+f"(c2), "+f"(c3)
        : "r"(a0), "r"(a1), "r"(a2), "r"(a3), "r"(b0), "r"(b1));
}

// ---------------- init: zero accumulators every call ----------------
__global__ void k_init() {
    int t = blockIdx.x * blockDim.x + threadIdx.x;
    if (t < HD) { g_colsum[t] = 0.f; g_colsumsq[t] = 0.f; }
    if (t < KC) g_count[t] = 0;
    if (t == 0) { g_zloss = 0.f; g_recon = 0.f; }
}

// ------------- cbprep: norms + bf16 pack + cbproj (1 kernel) --------------
__global__ __launch_bounds__(128) void k_cbprep(const float* __restrict__ cb,
                                                const float* __restrict__ W1,
                                                const float* __restrict__ B1) {
    __shared__ float row[DD];
    int tid = threadIdx.x, k = blockIdx.x;
    if (tid < 8) ((float4*)row)[tid] = ((const float4*)cb)[k * 8 + tid];
    __syncthreads();
    if (tid < 32) {
        float v = row[tid];
        if (tid < 16) g_cbbf[k * 16 + tid] = f2bf2(row[2 * tid], row[2 * tid + 1]);
        float s = v * v;
#pragma unroll
        for (int off = 16; off; off >>= 1) s += __shfl_xor_sync(0xffffffffu, s, off);
        if (tid == 0) g_cbnorm[k] = s;
    }
    float acc = B1[tid];
#pragma unroll
    for (int d = 0; d < DD; d++) acc = fmaf(row[d], W1[d * HD + tid], acc);
    g_cbproj[k * HD + tid] = acc;
}

// ------- GEMM1 (bf16 mma) + fused column stats: h1 = X@W + b --------------
// block tile 128m x 128n, K chunks of 32; 8 warps = 4m x 2n, warp 32m x 64n.
// smem bf16x2 [row][kpair] stride 20 -> conflict-free fragment loads.
__global__ __launch_bounds__(256, 2) void k_gemm1(const float* __restrict__ X,
                                                  const float* __restrict__ W,
                                                  const float* __restrict__ Bb) {
    __shared__ unsigned xs[128 * 20];
    __shared__ unsigned wts[128 * 20];
    __shared__ float ss[HD], ssq[HD];
    int tid = threadIdx.x, lane = tid & 31, warp = tid >> 5;
    int g = lane >> 2, t = lane & 3;
    int row0 = blockIdx.x * 128;
    int m0 = (warp >> 1) * 32;
    int n0w = (warp & 1) * 64;

    if (tid < HD) { ss[tid] = 0.f; ssq[tid] = 0.f; }

    float c[2][8][4];
#pragma unroll
    for (int i = 0; i < 2; i++)
#pragma unroll
        for (int j = 0; j < 8; j++)
#pragma unroll
            for (int q = 0; q < 4; q++) c[i][j][q] = 0.f;

    int xr = tid >> 1, xk = (tid & 1) * 16;     // floats
    const float* Xp = X + (row0 + xr) * DIN + xk;
    int wn = tid & 127, wk0 = (tid >> 7) * 16;  // floats

    // prefetch chunk 0
    float4 xv[4];
    float wv[16];
#pragma unroll
    for (int i = 0; i < 4; i++) xv[i] = *(const float4*)(Xp + 4 * i);
#pragma unroll
    for (int j = 0; j < 16; j++) wv[j] = W[(wk0 + j) * HD + wn];

    for (int kk = 0; kk < DIN; kk += 32) {
        __syncthreads();
#pragma unroll
        for (int i = 0; i < 4; i++) {
            xs[xr * 20 + (xk >> 1) + 2 * i]     = f2bf2(xv[i].x, xv[i].y);
            xs[xr * 20 + (xk >> 1) + 2 * i + 1] = f2bf2(xv[i].z, xv[i].w);
        }
#pragma unroll
        for (int i = 0; i < 8; i++)
            wts[wn * 20 + (wk0 >> 1) + i] = f2bf2(wv[2 * i], wv[2 * i + 1]);
        __syncthreads();

        // issue next chunk's global loads before MMA block (latency hiding)
        if (kk + 32 < DIN) {
#pragma unroll
            for (int i = 0; i < 4; i++) xv[i] = *(const float4*)(Xp + kk + 32 + 4 * i);
#pragma unroll
            for (int j = 0; j < 16; j++) wv[j] = W[(kk + 32 + wk0 + j) * HD + wn];
        }

#pragma unroll
        for (int s = 0; s < 2; s++) {
            unsigned a[2][4];
#pragma unroll
            for (int mt = 0; mt < 2; mt++) {
                int mr = m0 + mt * 16 + g;
                a[mt][0] = xs[mr * 20 + 8 * s + t];
                a[mt][1] = xs[(mr + 8) * 20 + 8 * s + t];
                a[mt][2] = xs[mr * 20 + 8 * s + t + 4];
                a[mt][3] = xs[(mr + 8) * 20 + 8 * s + t + 4];
            }
#pragma unroll
            for (int nt = 0; nt < 8; nt++) {
                int nc = n0w + nt * 8 + g;
                unsigned b0 = wts[nc * 20 + 8 * s + t];
                unsigned b1 = wts[nc * 20 + 8 * s + t + 4];
                mma_bf16(c[0][nt][0], c[0][nt][1], c[0][nt][2], c[0][nt][3],
                         a[0][0], a[0][1], a[0][2], a[0][3], b0, b1);
                mma_bf16(c[1][nt][0], c[1][nt][1], c[1][nt][2], c[1][nt][3],
                         a[1][0], a[1][1], a[1][2], a[1][3], b0, b1);
            }
        }
    }

    // epilogue: bias, bf16x2 store of h1, column stats
    int r0 = row0 + m0 + g;
#pragma unroll
    for (int nt = 0; nt < 8; nt++) {
        int col = n0w + nt * 8 + 2 * t;
        int u = (n0w >> 1) + nt * 4 + t;
        float b0v = Bb[col], b1v = Bb[col + 1];
        float v00 = c[0][nt][0] + b0v, v01 = c[0][nt][1] + b1v;
        float v02 = c[0][nt][2] + b0v, v03 = c[0][nt][3] + b1v;
        float v10 = c[1][nt][0] + b0v, v11 = c[1][nt][1] + b1v;
        float v12 = c[1][nt][2] + b0v, v13 = c[1][nt][3] + b1v;
        g_h1bf[r0 * 64 + u]        = f2bf2(v00, v01);
        g_h1bf[(r0 + 8) * 64 + u]  = f2bf2(v02, v03);
        g_h1bf[(r0 + 16) * 64 + u] = f2bf2(v10, v11);
        g_h1bf[(r0 + 24) * 64 + u] = f2bf2(v12, v13);
        atomicAdd(&ss[col],      v00 + v02 + v10 + v12);
        atomicAdd(&ss[col + 1],  v01 + v03 + v11 + v13);
        atomicAdd(&ssq[col],     v00 * v00 + v02 * v02 + v10 * v10 + v12 * v12);
        atomicAdd(&ssq[col + 1], v01 * v01 + v03 * v03 + v11 * v11 + v13 * v13);
    }
    __syncthreads();
    if (tid < HD) {
        atomicAdd(&g_colsum[tid], ss[tid]);
        atomicAdd(&g_colsumsq[tid], ssq[tid]);
    }
}

__global__ void k_bnfin(const float* __restrict__ G, const float* __restrict__ BE) {
    int j = threadIdx.x;
    float mean = g_colsum[j] * (1.f / (float)NR);
    float var  = g_colsumsq[j] * (1.f / (float)NR) - mean * mean;
    float sc = G[j] * rsqrtf(var + EPSBN);
    g_escale[j] = sc;
    g_eshift[j] = BE[j] - mean * sc;
}

// ------ FUSED: z = relu(bn(h1)) @ W2  -> distance argmin (z never hits mem)
// 512 threads, 256 rows/block. z C-fragments repacked directly into dist
// A-fragments; fp32 z copy kept in smem only for exact loss recompute.
__global__ __launch_bounds__(512) void k_fused(const float* __restrict__ cb,
                                               const float* __restrict__ W2,
                                               const float* __restrict__ B2) {
    extern __shared__ unsigned fsm[];
    unsigned* cbs = fsm;                        // 1024 x 20
    unsigned* as  = fsm + 20480;                // 256 x 68
    unsigned* wt  = fsm + 20480 + 17408;        // 32 x 68
    float* zsm = (float*)(fsm + 40064);         // 256 x 33 fp32
    float* cns = zsm + 256 * 33;                // 1024

    int tid = threadIdx.x, lane = tid & 31, warp = tid >> 5;
    int g = lane >> 2, t = lane & 3;
    int row0 = blockIdx.x * 256;

    // stage W2 -> [n][kpair] stride 68
#pragma unroll
    for (int i = 0; i < 4; i++) {
        int idx = tid + i * 512;
        int n = idx & 31, kp = idx >> 5;
        wt[n * 68 + kp] = f2bf2(W2[(2 * kp) * DD + n], W2[(2 * kp + 1) * DD + n]);
    }
    // stage codebook bf16x2 -> stride 20
#pragma unroll
    for (int i = 0; i < 8; i++) {
        int e = tid + i * 512;                  // uint4 index (4096)
        uint4 u = ((const uint4*)g_cbbf)[e];
        int n = e >> 2, kp0 = (e & 3) * 4;
        cbs[n * 20 + kp0]     = u.x;
        cbs[n * 20 + kp0 + 1] = u.y;
        cbs[n * 20 + kp0 + 2] = u.z;
        cbs[n * 20 + kp0 + 3] = u.w;
    }
#pragma unroll
    for (int i = 0; i < 2; i++) cns[tid + i * 512] = g_cbnorm[tid + i * 512];
    // stage activations: bf16 h1 -> BN -> ReLU -> bf16, stride 68
#pragma unroll
    for (int i = 0; i < 8; i++) {
        int e = tid + i * 512;                  // uint4 index (4096)
        int r = e >> 4, kp0 = (e & 15) * 4;
        uint4 u = *(const uint4*)&g_h1bf[(row0 + r) * 64 + kp0];
        float4 sc0 = __ldg((const float4*)&g_escale[2 * kp0]);
        float4 sc1 = __ldg((const float4*)&g_escale[2 * kp0 + 4]);
        float4 sh0 = __ldg((const float4*)&g_eshift[2 * kp0]);
        float4 sh1 = __ldg((const float4*)&g_eshift[2 * kp0 + 4]);
        uint4 o;
        o.x = f2bf2(fmaxf(fmaf(bflo(u.x), sc0.x, sh0.x), 0.f),
                    fmaxf(fmaf(bfhi(u.x), sc0.y, sh0.y), 0.f));
        o.y = f2bf2(fmaxf(fmaf(bflo(u.y), sc0.z, sh0.z), 0.f),
                    fmaxf(fmaf(bfhi(u.y), sc0.w, sh0.w), 0.f));
        o.z = f2bf2(fmaxf(fmaf(bflo(u.z), sc1.x, sh1.x), 0.f),
                    fmaxf(fmaf(bfhi(u.z), sc1.y, sh1.y), 0.f));
        o.w = f2bf2(fmaxf(fmaf(bflo(u.w), sc1.z, sh1.z), 0.f),
                    fmaxf(fmaf(bfhi(u.w), sc1.w, sh1.w), 0.f));
        *(uint4*)&as[r * 68 + kp0] = o;
    }
    __syncthreads();

    // ---- gemm2: per-warp 16 rows, z[16 x 32] in C fragments ----
    int m0 = warp * 16;
    float c[4][4];
#pragma unroll
    for (int nt = 0; nt < 4; nt++)
#pragma unroll
        for (int q = 0; q < 4; q++) c[nt][q] = 0.f;
#pragma unroll
    for (int s = 0; s < 8; s++) {
        int mr = m0 + g;
        unsigned a0 = as[mr * 68 + 8 * s + t];
        unsigned a1 = as[(mr + 8) * 68 + 8 * s + t];
        unsigned a2 = as[mr * 68 + 8 * s + t + 4];
        unsigned a3 = as[(mr + 8) * 68 + 8 * s + t + 4];
#pragma unroll
        for (int nt = 0; nt < 4; nt++) {
            unsigned b0 = wt[(nt * 8 + g) * 68 + 8 * s + t];
            unsigned b1 = wt[(nt * 8 + g) * 68 + 8 * s + t + 4];
            mma_bf16(c[nt][0], c[nt][1], c[nt][2], c[nt][3], a0, a1, a2, a3, b0, b1);
        }
    }
    // bias; fp32 copy to zsm; repack C-frags into dist A-frags
    int ra = m0 + g, rb = m0 + 8 + g;
    unsigned za[2][4];
#pragma unroll
    for (int nt = 0; nt < 4; nt++) {
        int col = nt * 8 + 2 * t;
        float b0v = B2[col], b1v = B2[col + 1];
        c[nt][0] += b0v; c[nt][1] += b1v; c[nt][2] += b0v; c[nt][3] += b1v;
        zsm[ra * 33 + col]     = c[nt][0];
        zsm[ra * 33 + col + 1] = c[nt][1];
        zsm[rb * 33 + col]     = c[nt][2];
        zsm[rb * 33 + col + 1] = c[nt][3];
    }
#pragma unroll
    for (int s = 0; s < 2; s++) {
        za[s][0] = f2bf2(c[2 * s][0],     c[2 * s][1]);      // row r,   k 16s+2t
        za[s][1] = f2bf2(c[2 * s][2],     c[2 * s][3]);      // row r+8
        za[s][2] = f2bf2(c[2 * s + 1][0], c[2 * s + 1][1]);  // row r,   k +8
        za[s][3] = f2bf2(c[2 * s + 1][2], c[2 * s + 1][3]);  // row r+8
    }
    __syncwarp();   // zsm rows of this warp written by its own lanes only

    // ---- distance sweep over 1024 codewords ----
    float bd0 = 3.4e38f, bdh = 3.4e38f;
    int bi0 = 0, bih = 0;
    for (int n0 = 0; n0 < KC / 8; n0++) {
        float d0 = 0.f, d1 = 0.f, d2 = 0.f, d3 = 0.f;
        int nb = (n0 * 8 + g) * 20 + t;
#pragma unroll
        for (int s = 0; s < 2; s++) {
            unsigned b0 = cbs[nb + 8 * s];
            unsigned b1 = cbs[nb + 8 * s + 4];
            mma_bf16(d0, d1, d2, d3, za[s][0], za[s][1], za[s][2], za[s][3], b0, b1);
        }
        int col0 = n0 * 8 + 2 * t;
        float cn0 = cns[col0], cn1 = cns[col0 + 1];
        float e0 = fmaf(d0, -2.f, cn0), e1 = fmaf(d1, -2.f, cn1);
        float f0 = fmaf(d2, -2.f, cn0), f1 = fmaf(d3, -2.f, cn1);
        if (e0 < bd0) { bd0 = e0; bi0 = col0; }
        if (e1 < bd0) { bd0 = e1; bi0 = col0 + 1; }
        if (f0 < bdh) { bdh = f0; bih = col0; }
        if (f1 < bdh) { bdh = f1; bih = col0 + 1; }
    }
    // (min, first-index) across the 4 lanes of each quad
#pragma unroll
    for (int off = 1; off <= 2; off <<= 1) {
        float od = __shfl_xor_sync(0xffffffffu, bd0, off);
        int   oi = __shfl_xor_sync(0xffffffffu, bi0, off);
        if (od < bd0 || (od == bd0 && oi < bi0)) { bd0 = od; bi0 = oi; }
        od = __shfl_xor_sync(0xffffffffu, bdh, off);
        oi = __shfl_xor_sync(0xffffffffu, bih, off);
        if (od < bdh || (od == bdh && oi < bih)) { bdh = od; bih = oi; }
    }

    float lsum = 0.f;
    if (t == 0) {
        int rl = m0 + g;
        int grow = row0 + rl;
        // exact fp32 recompute of the winning distances
        float zn0 = 0.f, dt0 = 0.f, zn1 = 0.f, dt1 = 0.f;
        const float* cb0 = cb + bi0 * DD;
        const float* cb1 = cb + bih * DD;
#pragma unroll
        for (int k = 0; k < DD; k++) {
            float z0 = zsm[rl * 33 + k];
            float z1 = zsm[(rl + 8) * 33 + k];
            zn0 += z0 * z0; dt0 = fmaf(z0, cb0[k], dt0);
            zn1 += z1 * z1; dt1 = fmaf(z1, cb1[k], dt1);
        }
        lsum = (zn0 + g_cbnorm[bi0] - 2.f * dt0) + (zn1 + g_cbnorm[bih] - 2.f * dt1);
        g_topic[grow] = bi0;
        g_topic[grow + 8] = bih;
        atomicAdd(&g_count[bi0], 1);
        atomicAdd(&g_count[bih], 1);
    }
#pragma unroll
    for (int off = 16; off; off >>= 1) lsum += __shfl_xor_sync(0xffffffffu, lsum, off);
    if (lane == 0) atomicAdd(&g_zloss, lsum);
}

// ---------------- decoder BN stats via topic histogram ----------------
__global__ __launch_bounds__(128) void k_decstats(const float* __restrict__ G,
                                                  const float* __restrict__ BE) {
    __shared__ float cnt[KC];
    int tid = threadIdx.x;
#pragma unroll
    for (int i = 0; i < 8; i++) cnt[tid + i * 128] = (float)g_count[tid + i * 128];
    __syncthreads();
    float s = 0.f, sq = 0.f;
    for (int k = 0; k < KC; k++) {
        float v = g_cbproj[k * HD + tid];
        float c = cnt[k];
        s += c * v;
        sq += c * v * v;
    }
    float mean = s * (1.f / (float)NR);
    float var  = sq * (1.f / (float)NR) - mean * mean;
    float sc = G[tid] * rsqrtf(var + EPSBN);
    g_dscale[tid] = sc;
    g_dshift[tid] = BE[tid] - mean * sc;
}

// ---------------- decoded = relu(bn(cbproj)) @ dec_w2 + b2  [1024,512] -----
__global__ __launch_bounds__(256) void k_decoded(const float* __restrict__ W2,
                                                 const float* __restrict__ B2) {
    __shared__ float as[16][HD];
    int tid = threadIdx.x;
    int k0 = blockIdx.x * 16;
#pragma unroll
    for (int i = 0; i < 8; i++) {
        int idx = tid + i * 256;
        int r = idx >> 7, j = idx & 127;
        float v = g_cbproj[(k0 + r) * HD + j];
        as[r][j] = fmaxf(fmaf(v, g_dscale[j], g_dshift[j]), 0.f);
    }
    __syncthreads();
    float acc0[16] = {}, acc1[16] = {};
    int c0 = tid, c1 = tid + 256;
    for (int j = 0; j < HD; j++) {
        float w0 = W2[j * DIN + c0];
        float w1 = W2[j * DIN + c1];
#pragma unroll
        for (int r = 0; r < 16; r++) {
            float a = as[r][j];
            acc0[r] = fmaf(a, w0, acc0[r]);
            acc1[r] = fmaf(a, w1, acc1[r]);
        }
    }
    float b0 = B2[c0], b1 = B2[c1];
#pragma unroll
    for (int r = 0; r < 16; r++) {
        g_decoded[(k0 + r) * DIN + c0] = acc0[r] + b0;
        g_decoded[(k0 + r) * DIN + c1] = acc1[r] + b1;
    }
}

// ---------------- recon: sum over all elements of (decoded[topic]-X)^2 -----
__global__ __launch_bounds__(256) void k_recon(const float* __restrict__ X) {
    int warp = threadIdx.x >> 5, lane = threadIdx.x & 31;
    float lsum = 0.f;
    int row0 = blockIdx.x * 128 + warp * 16;
    for (int rr = 0; rr < 16; rr++) {
        int row = row0 + rr;
        int t = g_topic[row];
        const float4* xr = (const float4*)X + row * 128;
        const float4* dr = (const float4*)g_decoded + t * 128;
#pragma unroll
        for (int i = 0; i < 4; i++) {
            float4 a = xr[lane + i * 32];
            float4 b = dr[lane + i * 32];
            float dx = a.x - b.x, dy = a.y - b.y, dz = a.z - b.z, dw = a.w - b.w;
            lsum += dx * dx + dy * dy + dz * dz + dw * dw;
        }
    }
#pragma unroll
    for (int off = 16; off; off >>= 1) lsum += __shfl_xor_sync(0xffffffffu, lsum, off);
    if (lane == 0) atomicAdd(&g_recon, lsum);
}

// ---------------- final scalar: 2*zloss + sqrt(recon) ----------------
__global__ void k_final(float* __restrict__ out) {
    out[0] = 2.f * g_zloss + sqrtf(g_recon);
}

// ---------------- launcher ----------------
extern "C" void kernel_launch(void* const* d_in, const int* in_sizes, int n_in,
                              void* d_out, int out_size) {
    const float* X    = (const float*)d_in[0];
    const float* ew1  = (const float*)d_in[1];
    const float* eb1  = (const float*)d_in[2];
    const float* eg1  = (const float*)d_in[3];
    const float* ebe1 = (const float*)d_in[4];
    const float* ew2  = (const float*)d_in[5];
    const float* eb2  = (const float*)d_in[6];
    const float* dw1  = (const float*)d_in[7];
    const float* db1  = (const float*)d_in[8];
    const float* dg1  = (const float*)d_in[9];
    const float* dbe1 = (const float*)d_in[10];
    const float* dw2  = (const float*)d_in[11];
    const float* db2  = (const float*)d_in[12];
    const float* cb   = (const float*)d_in[13];

    // cbs 20480 + as 17408 + wt 2176 + zsm 8448 + cns 1024 (x4 bytes)
    const int fusedSmem = (20480 + 17408 + 2176 + 8448 + 1024) * 4;
    cudaFuncSetAttribute(k_fused, cudaFuncAttributeMaxDynamicSharedMemorySize, fusedSmem);

    k_init<<<4, 256>>>();
    k_cbprep<<<KC, 128>>>(cb, dw1, db1);
    k_gemm1<<<NR / 128, 256>>>(X, ew1, eb1);
    k_bnfin<<<1, 128>>>(eg1, ebe1);
    k_fused<<<NR / 256, 512, fusedSmem>>>(cb, ew2, eb2);
    k_decstats<<<1, 128>>>(dg1, dbe1);
    k_decoded<<<KC / 16, 256>>>(dw2, db2);
    k_recon<<<NR / 128, 256>>>(X);
    k_final<<<1, 1>>>((float*)d_out);
}

// round 8
// speedup vs baseline: 2.6686x; 1.1238x over previous
#include <cuda_runtime.h>
#include <math.h>

// Problem sizes (fixed)
#define NR   65536
#define DIN  512
#define HD   128
#define DD   32
#define KC   1024
#define EPSBN 1e-5f

// ---------------- scratch (device globals; no allocations) ----------------
__device__ unsigned g_h1bf[NR * 64];     // encoder hidden pre-BN, bf16x2 (16.7 MB)
__device__ int      g_topic[NR];
__device__ float    g_colsum[HD];
__device__ float    g_colsumsq[HD];
__device__ float    g_escale[HD];
__device__ float    g_eshift[HD];
__device__ float    g_cbnorm[KC];
__device__ unsigned g_cbbf[KC * 16];     // codebook bf16x2 packed
__device__ float    g_cbproj[KC * HD];   // codebook @ dec_w1 + dec_b1
__device__ int      g_count[KC];
__device__ float    g_dscale[HD];
__device__ float    g_dshift[HD];
__device__ float    g_decoded[KC * DIN]; // decoded codewords (2 MB)
__device__ float    g_zloss;
__device__ float    g_recon;

// ---------------- bf16 helpers ----------------
__device__ __forceinline__ unsigned f2bf2(float lo, float hi) {
    unsigned r;
    asm("cvt.rn.bf16x2.f32 %0, %1, %2;" : "=r"(r) : "f"(hi), "f"(lo));
    return r;
}
__device__ __forceinline__ float bflo(unsigned u) { return __uint_as_float(u << 16); }
__device__ __forceinline__ float bfhi(unsigned u) { return __uint_as_float(u & 0xffff0000u); }

__device__ __forceinline__ void mma_bf16(float& c0, float& c1, float& c2, float& c3,
                                         unsigned a0, unsigned a1, unsigned a2, unsigned a3,
                                         unsigned b0, unsigned b1) {
    asm volatile(
        "mma.sync.aligned.m16n8k16.row.col.f32.bf16.bf16.f32 "
        "{%0,%1,%2,%3},{%4,%5,%6,%7},{%8,%9},{%0,%1,%2,%3};"
        : "+f"(c0), "+f"(c1), "+f"(c2), "+f"(c3)
        : "r"(a0), "r"(a1), "r"(a2), "r"(a3), "r"(b0), "r"(b1));
}

// ------ cbprep: init accumulators + norms + bf16 pack + cbproj (1 kernel) --
// stream order guarantees all zeroing is complete before gemm1 starts.
__global__ __launch_bounds__(128) void k_cbprep(const float* __restrict__ cb,
                                                const float* __restrict__ W1,
                                                const float* __restrict__ B1) {
    __shared__ float row[DD];
    int tid = threadIdx.x, k = blockIdx.x;
    if (tid == 0) g_count[k] = 0;
    if (k == 0) {
        if (tid < HD) { g_colsum[tid] = 0.f; g_colsumsq[tid] = 0.f; }
        if (tid == 0) { g_zloss = 0.f; g_recon = 0.f; }
    }
    if (tid < 8) ((float4*)row)[tid] = ((const float4*)cb)[k * 8 + tid];
    __syncthreads();
    if (tid < 32) {
        float v = row[tid];
        if (tid < 16) g_cbbf[k * 16 + tid] = f2bf2(row[2 * tid], row[2 * tid + 1]);
        float s = v * v;
#pragma unroll
        for (int off = 16; off; off >>= 1) s += __shfl_xor_sync(0xffffffffu, s, off);
        if (tid == 0) g_cbnorm[k] = s;
    }
    float acc = B1[tid];
#pragma unroll
    for (int d = 0; d < DD; d++) acc = fmaf(row[d], W1[d * HD + tid], acc);
    g_cbproj[k * HD + tid] = acc;
}

// ------- GEMM1 (bf16 mma) + fused column stats: h1 = X@W + b --------------
// block tile 128m x 128n, K chunks of 32; 8 warps = 4m x 2n, warp 32m x 64n.
// double-buffered smem (one sync per chunk); stats shfl-reduced before atomics.
__global__ __launch_bounds__(256, 2) void k_gemm1(const float* __restrict__ X,
                                                  const float* __restrict__ W,
                                                  const float* __restrict__ Bb) {
    __shared__ unsigned xs[2][128 * 20];
    __shared__ unsigned wts[2][128 * 20];
    __shared__ float ss[HD], ssq[HD];
    int tid = threadIdx.x, lane = tid & 31, warp = tid >> 5;
    int g = lane >> 2, t = lane & 3;
    int row0 = blockIdx.x * 128;
    int m0 = (warp >> 1) * 32;
    int n0w = (warp & 1) * 64;

    if (tid < HD) { ss[tid] = 0.f; ssq[tid] = 0.f; }

    float c[2][8][4];
#pragma unroll
    for (int i = 0; i < 2; i++)
#pragma unroll
        for (int j = 0; j < 8; j++)
#pragma unroll
            for (int q = 0; q < 4; q++) c[i][j][q] = 0.f;

    int xr = tid >> 1, xk = (tid & 1) * 16;     // floats
    const float* Xp = X + (row0 + xr) * DIN + xk;
    int wn = tid & 127, wk0 = (tid >> 7) * 16;  // floats

    // load + stage chunk 0 into buffer 0
    float4 xv[4];
    float wv[16];
#pragma unroll
    for (int i = 0; i < 4; i++) xv[i] = *(const float4*)(Xp + 4 * i);
#pragma unroll
    for (int j = 0; j < 16; j++) wv[j] = W[(wk0 + j) * HD + wn];
#pragma unroll
    for (int i = 0; i < 4; i++) {
        xs[0][xr * 20 + (xk >> 1) + 2 * i]     = f2bf2(xv[i].x, xv[i].y);
        xs[0][xr * 20 + (xk >> 1) + 2 * i + 1] = f2bf2(xv[i].z, xv[i].w);
    }
#pragma unroll
    for (int i = 0; i < 8; i++)
        wts[0][wn * 20 + (wk0 >> 1) + i] = f2bf2(wv[2 * i], wv[2 * i + 1]);
    __syncthreads();

    int p = 0;
    for (int kk = 0; kk < DIN; kk += 32) {
        bool more = (kk + 32 < DIN);
        // issue next chunk's global loads first (hidden under the MMA block)
        if (more) {
#pragma unroll
            for (int i = 0; i < 4; i++) xv[i] = *(const float4*)(Xp + kk + 32 + 4 * i);
#pragma unroll
            for (int j = 0; j < 16; j++) wv[j] = W[(kk + 32 + wk0 + j) * HD + wn];
        }

#pragma unroll
        for (int s = 0; s < 2; s++) {
            unsigned a[2][4];
#pragma unroll
            for (int mt = 0; mt < 2; mt++) {
                int mr = m0 + mt * 16 + g;
                a[mt][0] = xs[p][mr * 20 + 8 * s + t];
                a[mt][1] = xs[p][(mr + 8) * 20 + 8 * s + t];
                a[mt][2] = xs[p][mr * 20 + 8 * s + t + 4];
                a[mt][3] = xs[p][(mr + 8) * 20 + 8 * s + t + 4];
            }
#pragma unroll
            for (int nt = 0; nt < 8; nt++) {
                int nc = n0w + nt * 8 + g;
                unsigned b0 = wts[p][nc * 20 + 8 * s + t];
                unsigned b1 = wts[p][nc * 20 + 8 * s + t + 4];
                mma_bf16(c[0][nt][0], c[0][nt][1], c[0][nt][2], c[0][nt][3],
                         a[0][0], a[0][1], a[0][2], a[0][3], b0, b1);
                mma_bf16(c[1][nt][0], c[1][nt][1], c[1][nt][2], c[1][nt][3],
                         a[1][0], a[1][1], a[1][2], a[1][3], b0, b1);
            }
        }

        // stage next chunk into the other buffer (safe: last readers of p^1
        // were separated by the previous sync)
        if (more) {
            int q = p ^ 1;
#pragma unroll
            for (int i = 0; i < 4; i++) {
                xs[q][xr * 20 + (xk >> 1) + 2 * i]     = f2bf2(xv[i].x, xv[i].y);
                xs[q][xr * 20 + (xk >> 1) + 2 * i + 1] = f2bf2(xv[i].z, xv[i].w);
            }
#pragma unroll
            for (int i = 0; i < 8; i++)
                wts[q][wn * 20 + (wk0 >> 1) + i] = f2bf2(wv[2 * i], wv[2 * i + 1]);
        }
        __syncthreads();
        p ^= 1;
    }

    // epilogue: bias, bf16x2 store of h1, column stats (shfl-reduced)
    int r0 = row0 + m0 + g;
#pragma unroll
    for (int nt = 0; nt < 8; nt++) {
        int col = n0w + nt * 8 + 2 * t;
        int u = (n0w >> 1) + nt * 4 + t;
        float b0v = Bb[col], b1v = Bb[col + 1];
        float v00 = c[0][nt][0] + b0v, v01 = c[0][nt][1] + b1v;
        float v02 = c[0][nt][2] + b0v, v03 = c[0][nt][3] + b1v;
        float v10 = c[1][nt][0] + b0v, v11 = c[1][nt][1] + b1v;
        float v12 = c[1][nt][2] + b0v, v13 = c[1][nt][3] + b1v;
        g_h1bf[r0 * 64 + u]        = f2bf2(v00, v01);
        g_h1bf[(r0 + 8) * 64 + u]  = f2bf2(v02, v03);
        g_h1bf[(r0 + 16) * 64 + u] = f2bf2(v10, v11);
        g_h1bf[(r0 + 24) * 64 + u] = f2bf2(v12, v13);
        float s0 = v00 + v02 + v10 + v12;
        float s1 = v01 + v03 + v11 + v13;
        float q0 = v00 * v00 + v02 * v02 + v10 * v10 + v12 * v12;
        float q1 = v01 * v01 + v03 * v03 + v11 * v11 + v13 * v13;
        // reduce over the g dimension (lanes t, t+4, ..., t+28 share col)
#pragma unroll
        for (int off = 4; off <= 16; off <<= 1) {
            s0 += __shfl_xor_sync(0xffffffffu, s0, off);
            s1 += __shfl_xor_sync(0xffffffffu, s1, off);
            q0 += __shfl_xor_sync(0xffffffffu, q0, off);
            q1 += __shfl_xor_sync(0xffffffffu, q1, off);
        }
        if (g == 0) {
            atomicAdd(&ss[col],      s0);
            atomicAdd(&ss[col + 1],  s1);
            atomicAdd(&ssq[col],     q0);
            atomicAdd(&ssq[col + 1], q1);
        }
    }
    __syncthreads();
    if (tid < HD) {
        atomicAdd(&g_colsum[tid], ss[tid]);
        atomicAdd(&g_colsumsq[tid], ssq[tid]);
    }
}

__global__ void k_bnfin(const float* __restrict__ G, const float* __restrict__ BE) {
    int j = threadIdx.x;
    float mean = g_colsum[j] * (1.f / (float)NR);
    float var  = g_colsumsq[j] * (1.f / (float)NR) - mean * mean;
    float sc = G[j] * rsqrtf(var + EPSBN);
    g_escale[j] = sc;
    g_eshift[j] = BE[j] - mean * sc;
}

// ------ FUSED: z = relu(bn(h1)) @ W2  -> distance argmin (z never hits mem)
__global__ __launch_bounds__(512) void k_fused(const float* __restrict__ cb,
                                               const float* __restrict__ W2,
                                               const float* __restrict__ B2) {
    extern __shared__ unsigned fsm[];
    unsigned* cbs = fsm;                        // 1024 x 20
    unsigned* as  = fsm + 20480;                // 256 x 68
    unsigned* wt  = fsm + 20480 + 17408;        // 32 x 68
    float* zsm = (float*)(fsm + 40064);         // 256 x 33 fp32
    float* cns = zsm + 256 * 33;                // 1024

    int tid = threadIdx.x, lane = tid & 31, warp = tid >> 5;
    int g = lane >> 2, t = lane & 3;
    int row0 = blockIdx.x * 256;

    // stage W2 -> [n][kpair] stride 68
#pragma unroll
    for (int i = 0; i < 4; i++) {
        int idx = tid + i * 512;
        int n = idx & 31, kp = idx >> 5;
        wt[n * 68 + kp] = f2bf2(W2[(2 * kp) * DD + n], W2[(2 * kp + 1) * DD + n]);
    }
    // stage codebook bf16x2 -> stride 20
#pragma unroll
    for (int i = 0; i < 8; i++) {
        int e = tid + i * 512;                  // uint4 index (4096)
        uint4 u = ((const uint4*)g_cbbf)[e];
        int n = e >> 2, kp0 = (e & 3) * 4;
        cbs[n * 20 + kp0]     = u.x;
        cbs[n * 20 + kp0 + 1] = u.y;
        cbs[n * 20 + kp0 + 2] = u.z;
        cbs[n * 20 + kp0 + 3] = u.w;
    }
#pragma unroll
    for (int i = 0; i < 2; i++) cns[tid + i * 512] = g_cbnorm[tid + i * 512];
    // stage activations: bf16 h1 -> BN -> ReLU -> bf16, stride 68
#pragma unroll
    for (int i = 0; i < 8; i++) {
        int e = tid + i * 512;                  // uint4 index (4096)
        int r = e >> 4, kp0 = (e & 15) * 4;
        uint4 u = *(const uint4*)&g_h1bf[(row0 + r) * 64 + kp0];
        float4 sc0 = __ldg((const float4*)&g_escale[2 * kp0]);
        float4 sc1 = __ldg((const float4*)&g_escale[2 * kp0 + 4]);
        float4 sh0 = __ldg((const float4*)&g_eshift[2 * kp0]);
        float4 sh1 = __ldg((const float4*)&g_eshift[2 * kp0 + 4]);
        uint4 o;
        o.x = f2bf2(fmaxf(fmaf(bflo(u.x), sc0.x, sh0.x), 0.f),
                    fmaxf(fmaf(bfhi(u.x), sc0.y, sh0.y), 0.f));
        o.y = f2bf2(fmaxf(fmaf(bflo(u.y), sc0.z, sh0.z), 0.f),
                    fmaxf(fmaf(bfhi(u.y), sc0.w, sh0.w), 0.f));
        o.z = f2bf2(fmaxf(fmaf(bflo(u.z), sc1.x, sh1.x), 0.f),
                    fmaxf(fmaf(bfhi(u.z), sc1.y, sh1.y), 0.f));
        o.w = f2bf2(fmaxf(fmaf(bflo(u.w), sc1.z, sh1.z), 0.f),
                    fmaxf(fmaf(bfhi(u.w), sc1.w, sh1.w), 0.f));
        *(uint4*)&as[r * 68 + kp0] = o;
    }
    __syncthreads();

    // ---- gemm2: per-warp 16 rows, z[16 x 32] in C fragments ----
    int m0 = warp * 16;
    float c[4][4];
#pragma unroll
    for (int nt = 0; nt < 4; nt++)
#pragma unroll
        for (int q = 0; q < 4; q++) c[nt][q] = 0.f;
#pragma unroll
    for (int s = 0; s < 8; s++) {
        int mr = m0 + g;
        unsigned a0 = as[mr * 68 + 8 * s + t];
        unsigned a1 = as[(mr + 8) * 68 + 8 * s + t];
        unsigned a2 = as[mr * 68 + 8 * s + t + 4];
        unsigned a3 = as[(mr + 8) * 68 + 8 * s + t + 4];
#pragma unroll
        for (int nt = 0; nt < 4; nt++) {
            unsigned b0 = wt[(nt * 8 + g) * 68 + 8 * s + t];
            unsigned b1 = wt[(nt * 8 + g) * 68 + 8 * s + t + 4];
            mma_bf16(c[nt][0], c[nt][1], c[nt][2], c[nt][3], a0, a1, a2, a3, b0, b1);
        }
    }
    // bias; fp32 copy to zsm; repack C-frags into dist A-frags
    int ra = m0 + g, rb = m0 + 8 + g;
    unsigned za[2][4];
#pragma unroll
    for (int nt = 0; nt < 4; nt++) {
        int col = nt * 8 + 2 * t;
        float b0v = B2[col], b1v = B2[col + 1];
        c[nt][0] += b0v; c[nt][1] += b1v; c[nt][2] += b0v; c[nt][3] += b1v;
        zsm[ra * 33 + col]     = c[nt][0];
        zsm[ra * 33 + col + 1] = c[nt][1];
        zsm[rb * 33 + col]     = c[nt][2];
        zsm[rb * 33 + col + 1] = c[nt][3];
    }
#pragma unroll
    for (int s = 0; s < 2; s++) {
        za[s][0] = f2bf2(c[2 * s][0],     c[2 * s][1]);
        za[s][1] = f2bf2(c[2 * s][2],     c[2 * s][3]);
        za[s][2] = f2bf2(c[2 * s + 1][0], c[2 * s + 1][1]);
        za[s][3] = f2bf2(c[2 * s + 1][2], c[2 * s + 1][3]);
    }
    __syncwarp();   // zsm rows of this warp written by its own lanes only

    // ---- distance sweep over 1024 codewords ----
    float bd0 = 3.4e38f, bdh = 3.4e38f;
    int bi0 = 0, bih = 0;
    for (int n0 = 0; n0 < KC / 8; n0++) {
        float d0 = 0.f, d1 = 0.f, d2 = 0.f, d3 = 0.f;
        int nb = (n0 * 8 + g) * 20 + t;
#pragma unroll
        for (int s = 0; s < 2; s++) {
            unsigned b0 = cbs[nb + 8 * s];
            unsigned b1 = cbs[nb + 8 * s + 4];
            mma_bf16(d0, d1, d2, d3, za[s][0], za[s][1], za[s][2], za[s][3], b0, b1);
        }
        int col0 = n0 * 8 + 2 * t;
        float cn0 = cns[col0], cn1 = cns[col0 + 1];
        float e0 = fmaf(d0, -2.f, cn0), e1 = fmaf(d1, -2.f, cn1);
        float f0 = fmaf(d2, -2.f, cn0), f1 = fmaf(d3, -2.f, cn1);
        if (e0 < bd0) { bd0 = e0; bi0 = col0; }
        if (e1 < bd0) { bd0 = e1; bi0 = col0 + 1; }
        if (f0 < bdh) { bdh = f0; bih = col0; }
        if (f1 < bdh) { bdh = f1; bih = col0 + 1; }
    }
    // (min, first-index) across the 4 lanes of each quad
#pragma unroll
    for (int off = 1; off <= 2; off <<= 1) {
        float od = __shfl_xor_sync(0xffffffffu, bd0, off);
        int   oi = __shfl_xor_sync(0xffffffffu, bi0, off);
        if (od < bd0 || (od == bd0 && oi < bi0)) { bd0 = od; bi0 = oi; }
        od = __shfl_xor_sync(0xffffffffu, bdh, off);
        oi = __shfl_xor_sync(0xffffffffu, bih, off);
        if (od < bdh || (od == bdh && oi < bih)) { bdh = od; bih = oi; }
    }

    float lsum = 0.f;
    if (t == 0) {
        int rl = m0 + g;
        int grow = row0 + rl;
        // exact fp32 recompute of the winning distances
        float zn0 = 0.f, dt0 = 0.f, zn1 = 0.f, dt1 = 0.f;
        const float* cb0 = cb + bi0 * DD;
        const float* cb1 = cb + bih * DD;
#pragma unroll
        for (int k = 0; k < DD; k++) {
            float z0 = zsm[rl * 33 + k];
            float z1 = zsm[(rl + 8) * 33 + k];
            zn0 += z0 * z0; dt0 = fmaf(z0, cb0[k], dt0);
            zn1 += z1 * z1; dt1 = fmaf(z1, cb1[k], dt1);
        }
        lsum = (zn0 + g_cbnorm[bi0] - 2.f * dt0) + (zn1 + g_cbnorm[bih] - 2.f * dt1);
        g_topic[grow] = bi0;
        g_topic[grow + 8] = bih;
        atomicAdd(&g_count[bi0], 1);
        atomicAdd(&g_count[bih], 1);
    }
#pragma unroll
    for (int off = 16; off; off >>= 1) lsum += __shfl_xor_sync(0xffffffffu, lsum, off);
    if (lane == 0) atomicAdd(&g_zloss, lsum);
}

// ---------------- decoder BN stats via topic histogram ----------------
__global__ __launch_bounds__(128) void k_decstats(const float* __restrict__ G,
                                                  const float* __restrict__ BE) {
    __shared__ float cnt[KC];
    int tid = threadIdx.x;
#pragma unroll
    for (int i = 0; i < 8; i++) cnt[tid + i * 128] = (float)g_count[tid + i * 128];
    __syncthreads();
    float s = 0.f, sq = 0.f;
    for (int k = 0; k < KC; k++) {
        float v = g_cbproj[k * HD + tid];
        float c = cnt[k];
        s += c * v;
        sq += c * v * v;
    }
    float mean = s * (1.f / (float)NR);
    float var  = sq * (1.f / (float)NR) - mean * mean;
    float sc = G[tid] * rsqrtf(var + EPSBN);
    g_dscale[tid] = sc;
    g_dshift[tid] = BE[tid] - mean * sc;
}

// ---------------- decoded = relu(bn(cbproj)) @ dec_w2 + b2  [1024,512] -----
__global__ __launch_bounds__(256) void k_decoded(const float* __restrict__ W2,
                                                 const float* __restrict__ B2) {
    __shared__ float as[16][HD];
    int tid = threadIdx.x;
    int k0 = blockIdx.x * 16;
#pragma unroll
    for (int i = 0; i < 8; i++) {
        int idx = tid + i * 256;
        int r = idx >> 7, j = idx & 127;
        float v = g_cbproj[(k0 + r) * HD + j];
        as[r][j] = fmaxf(fmaf(v, g_dscale[j], g_dshift[j]), 0.f);
    }
    __syncthreads();
    float acc0[16] = {}, acc1[16] = {};
    int c0 = tid, c1 = tid + 256;
    for (int j = 0; j < HD; j++) {
        float w0 = W2[j * DIN + c0];
        float w1 = W2[j * DIN + c1];
#pragma unroll
        for (int r = 0; r < 16; r++) {
            float a = as[r][j];
            acc0[r] = fmaf(a, w0, acc0[r]);
            acc1[r] = fmaf(a, w1, acc1[r]);
        }
    }
    float b0 = B2[c0], b1 = B2[c1];
#pragma unroll
    for (int r = 0; r < 16; r++) {
        g_decoded[(k0 + r) * DIN + c0] = acc0[r] + b0;
        g_decoded[(k0 + r) * DIN + c1] = acc1[r] + b1;
    }
}

// ---------------- recon: sum over all elements of (decoded[topic]-X)^2 -----
// 2 rows in flight per warp -> 16 outstanding float4 loads (MLP)
__global__ __launch_bounds__(256) void k_recon(const float* __restrict__ X) {
    int warp = threadIdx.x >> 5, lane = threadIdx.x & 31;
    float lsum = 0.f;
    int row0 = blockIdx.x * 128 + warp * 16;
    for (int rr = 0; rr < 16; rr += 2) {
        int rowa = row0 + rr, rowb = rowa + 1;
        int ta = g_topic[rowa], tb = g_topic[rowb];
        const float4* xa = (const float4*)X + rowa * 128;
        const float4* xb = (const float4*)X + rowb * 128;
        const float4* da = (const float4*)g_decoded + ta * 128;
        const float4* db = (const float4*)g_decoded + tb * 128;
#pragma unroll
        for (int i = 0; i < 4; i++) {
            float4 a0 = xa[lane + i * 32];
            float4 b0 = da[lane + i * 32];
            float4 a1 = xb[lane + i * 32];
            float4 b1 = db[lane + i * 32];
            float dx = a0.x - b0.x, dy = a0.y - b0.y, dz = a0.z - b0.z, dw = a0.w - b0.w;
            lsum += dx * dx + dy * dy + dz * dz + dw * dw;
            dx = a1.x - b1.x; dy = a1.y - b1.y; dz = a1.z - b1.z; dw = a1.w - b1.w;
            lsum += dx * dx + dy * dy + dz * dz + dw * dw;
        }
    }
#pragma unroll
    for (int off = 16; off; off >>= 1) lsum += __shfl_xor_sync(0xffffffffu, lsum, off);
    if (lane == 0) atomicAdd(&g_recon, lsum);
}

// ---------------- final scalar: 2*zloss + sqrt(recon) ----------------
__global__ void k_final(float* __restrict__ out) {
    out[0] = 2.f * g_zloss + sqrtf(g_recon);
}

// ---------------- launcher ----------------
extern "C" void kernel_launch(void* const* d_in, const int* in_sizes, int n_in,
                              void* d_out, int out_size) {
    const float* X    = (const float*)d_in[0];
    const float* ew1  = (const float*)d_in[1];
    const float* eb1  = (const float*)d_in[2];
    const float* eg1  = (const float*)d_in[3];
    const float* ebe1 = (const float*)d_in[4];
    const float* ew2  = (const float*)d_in[5];
    const float* eb2  = (const float*)d_in[6];
    const float* dw1  = (const float*)d_in[7];
    const float* db1  = (const float*)d_in[8];
    const float* dg1  = (const float*)d_in[9];
    const float* dbe1 = (const float*)d_in[10];
    const float* dw2  = (const float*)d_in[11];
    const float* db2  = (const float*)d_in[12];
    const float* cb   = (const float*)d_in[13];

    // cbs 20480 + as 17408 + wt 2176 + zsm 8448 + cns 1024 (x4 bytes)
    const int fusedSmem = (20480 + 17408 + 2176 + 8448 + 1024) * 4;
    cudaFuncSetAttribute(k_fused, cudaFuncAttributeMaxDynamicSharedMemorySize, fusedSmem);

    k_cbprep<<<KC, 128>>>(cb, dw1, db1);
    k_gemm1<<<NR / 128, 256>>>(X, ew1, eb1);
    k_bnfin<<<1, 128>>>(eg1, ebe1);
    k_fused<<<NR / 256, 512, fusedSmem>>>(cb, ew2, eb2);
    k_decstats<<<1, 128>>>(dg1, dbe1);
    k_decoded<<<KC / 16, 256>>>(dw2, db2);
    k_recon<<<NR / 128, 256>>>(X);
    k_final<<<1, 1>>>((float*)d_out);
}